// round 2
// baseline (speedup 1.0000x reference)
#include <cuda_runtime.h>
#include <math.h>
#include <float.h>

// ---------------------------------------------------------------------------
// Problem constants
//   b=8, n=4096, d=512, h=8, dh=64, m=256 landmarks, l=16, 3*h*dh=1536
// ---------------------------------------------------------------------------
#define B_SZ     8
#define N_TOK    4096
#define DIM      512
#define HEADS    8
#define DH       64
#define M_LM     256
#define L_PER    16
#define E3       1536
#define BN       (B_SZ * N_TOK)         // 32768
#define BHN      (B_SZ * HEADS)         // 64
#define KER      33

// ---------------------------------------------------------------------------
// Device scratch (static — no allocations allowed)
// ---------------------------------------------------------------------------
__device__ __align__(256) float g_xn   [BN * DIM];                 // 64 MB
__device__ __align__(256) float g_qkv  [BN * E3];                  // 201 MB
__device__ __align__(256) float g_ql   [BHN * M_LM * DH];
__device__ __align__(256) float g_kl   [BHN * M_LM * DH];
__device__ __align__(256) float g_attn1[BHN * N_TOK * M_LM];       // 268 MB
__device__ __align__(256) float g_attn3[BHN * M_LM * N_TOK];       // 268 MB
__device__ __align__(256) float g_o1   [BHN * N_TOK * M_LM];       // 268 MB
__device__ __align__(256) float g_a2   [BHN * M_LM * M_LM];
__device__ __align__(256) float g_z    [BHN * M_LM * M_LM];
__device__ __align__(256) float g_z2   [BHN * M_LM * M_LM];
__device__ __align__(256) float g_az   [BHN * M_LM * M_LM];
__device__ __align__(256) float g_t1   [BHN * M_LM * M_LM];
__device__ __align__(256) float g_t2   [BHN * M_LM * M_LM];
__device__ __align__(256) float g_kv   [BHN * M_LM * DH];
__device__ __align__(256) float g_y    [BN * DIM];                 // 64 MB
__device__ __align__(256) float g_scal [2];

// ---------------------------------------------------------------------------
// Block reductions (blockDim.x == 256)
// ---------------------------------------------------------------------------
__device__ __forceinline__ float bredSum(float v, float* sm) {
    #pragma unroll
    for (int o = 16; o; o >>= 1) v += __shfl_xor_sync(0xffffffffu, v, o);
    int w = threadIdx.x >> 5, l = threadIdx.x & 31;
    if (l == 0) sm[w] = v;
    __syncthreads();
    if (w == 0) {
        v = (l < 8) ? sm[l] : 0.0f;
        #pragma unroll
        for (int o = 4; o; o >>= 1) v += __shfl_xor_sync(0xffffffffu, v, o);
        if (l == 0) sm[0] = v;
    }
    __syncthreads();
    v = sm[0];
    __syncthreads();
    return v;
}

__device__ __forceinline__ float bredMax(float v, float* sm) {
    #pragma unroll
    for (int o = 16; o; o >>= 1) v = fmaxf(v, __shfl_xor_sync(0xffffffffu, v, o));
    int w = threadIdx.x >> 5, l = threadIdx.x & 31;
    if (l == 0) sm[w] = v;
    __syncthreads();
    if (w == 0) {
        v = (l < 8) ? sm[l] : -FLT_MAX;
        #pragma unroll
        for (int o = 4; o; o >>= 1) v = fmaxf(v, __shfl_xor_sync(0xffffffffu, v, o));
        if (l == 0) sm[0] = v;
    }
    __syncthreads();
    v = sm[0];
    __syncthreads();
    return v;
}

// ---------------------------------------------------------------------------
// LayerNorm: one block (256 threads) per row of 512
// ---------------------------------------------------------------------------
__global__ void ln_kernel(const float* __restrict__ x, const float* __restrict__ w,
                          const float* __restrict__ bias, float* __restrict__ o) {
    __shared__ float sm[32];
    long long row = blockIdx.x;
    const float2* xr = (const float2*)(x + row * DIM);
    int t = threadIdx.x;
    float2 v = xr[t];
    float mu = bredSum(v.x + v.y, sm) * (1.0f / DIM);
    float d0 = v.x - mu, d1 = v.y - mu;
    float var = bredSum(d0 * d0 + d1 * d1, sm) * (1.0f / DIM);
    float rs = rsqrtf(var + 1e-5f);
    float2 wv = ((const float2*)w)[t];
    float2 bv = ((const float2*)bias)[t];
    float2* orow = (float2*)(o + row * DIM);
    orow[t] = make_float2(d0 * rs * wv.x + bv.x, d1 * rs * wv.y + bv.y);
}

// ---------------------------------------------------------------------------
// Generic batched GEMM: C = alpha * Amat (.) op(Bmat), row-major, dims aligned
// (M,N mult of 64; K mult of 16). Batch index z decomposes: zo=z/Hdiv, zi=z%Hdiv.
// ---------------------------------------------------------------------------
template <bool TRANSB>
__global__ void __launch_bounds__(256)
gemm_kernel(const float* __restrict__ Amat, const float* __restrict__ Bmat,
            float* __restrict__ Cmat, int K, int lda, int ldb, int ldc,
            long long sAo, long long sAi, long long sBo, long long sBi,
            long long sCo, long long sCi, int Hdiv, float alpha) {
    __shared__ float As[16][64];
    __shared__ float Bs[16][64];
    int z = blockIdx.z;
    int zo = z / Hdiv, zi = z - zo * Hdiv;
    Amat += zo * sAo + zi * sAi;
    Bmat += zo * sBo + zi * sBi;
    Cmat += zo * sCo + zi * sCi;
    int m0 = blockIdx.y * 64, n0 = blockIdx.x * 64;
    int tid = threadIdx.x;
    int tx = tid & 15, ty = tid >> 4;
    int lrow = tid >> 2;            // 0..63
    int lk4  = (tid & 3) << 2;      // 0,4,8,12
    int brow = tid >> 4;            // 0..15
    int bcol = (tid & 15) << 2;     // 0..60

    float acc[4][4] = {};
    for (int k0 = 0; k0 < K; k0 += 16) {
        float4 a4 = *(const float4*)(Amat + (long long)(m0 + lrow) * lda + k0 + lk4);
        As[lk4 + 0][lrow] = a4.x; As[lk4 + 1][lrow] = a4.y;
        As[lk4 + 2][lrow] = a4.z; As[lk4 + 3][lrow] = a4.w;
        if (TRANSB) {
            float4 b4 = *(const float4*)(Bmat + (long long)(n0 + lrow) * ldb + k0 + lk4);
            Bs[lk4 + 0][lrow] = b4.x; Bs[lk4 + 1][lrow] = b4.y;
            Bs[lk4 + 2][lrow] = b4.z; Bs[lk4 + 3][lrow] = b4.w;
        } else {
            float4 b4 = *(const float4*)(Bmat + (long long)(k0 + brow) * ldb + n0 + bcol);
            *(float4*)&Bs[brow][bcol] = b4;
        }
        __syncthreads();
        #pragma unroll
        for (int kk = 0; kk < 16; kk++) {
            float4 av = *(const float4*)&As[kk][ty << 2];
            float4 bv = *(const float4*)&Bs[kk][tx << 2];
            float aa[4] = {av.x, av.y, av.z, av.w};
            float bb[4] = {bv.x, bv.y, bv.z, bv.w};
            #pragma unroll
            for (int i = 0; i < 4; i++)
                #pragma unroll
                for (int j = 0; j < 4; j++)
                    acc[i][j] += aa[i] * bb[j];
        }
        __syncthreads();
    }
    #pragma unroll
    for (int i = 0; i < 4; i++) {
        float4 o;
        o.x = acc[i][0] * alpha; o.y = acc[i][1] * alpha;
        o.z = acc[i][2] * alpha; o.w = acc[i][3] * alpha;
        *(float4*)(Cmat + (long long)(m0 + (ty << 2) + i) * ldc + n0 + (tx << 2)) = o;
    }
}

static inline void launch_gemm(bool transB, const float* Amat, const float* Bmat,
                               float* Cmat, int M, int N, int K,
                               int lda, int ldb, int ldc,
                               long long sAo, long long sAi, long long sBo, long long sBi,
                               long long sCo, long long sCi, int Hdiv, int batch,
                               float alpha) {
    dim3 grid(N / 64, M / 64, batch), block(256);
    if (transB)
        gemm_kernel<true><<<grid, block>>>(Amat, Bmat, Cmat, K, lda, ldb, ldc,
                                           sAo, sAi, sBo, sBi, sCo, sCi, Hdiv, alpha);
    else
        gemm_kernel<false><<<grid, block>>>(Amat, Bmat, Cmat, K, lda, ldb, ldc,
                                            sAo, sAi, sBo, sBi, sCo, sCi, Hdiv, alpha);
}

// ---------------------------------------------------------------------------
// Landmark means: q_l (scaled by dh^-0.5) and k_l from packed qkv
// ---------------------------------------------------------------------------
__global__ void landmark_kernel(const float* __restrict__ qkv,
                                float* __restrict__ ql, float* __restrict__ kl) {
    int idx = blockIdx.x * 256 + threadIdx.x;        // over 64*256*64
    int d  = idx & 63;
    int mi = (idx >> 6) & 255;
    int bh = idx >> 14;
    int bb = bh >> 3, h = bh & 7;
    const float* base = qkv + ((long long)(bb * N_TOK + mi * L_PER)) * E3 + h * DH + d;
    float sq = 0.f, sk = 0.f;
    #pragma unroll
    for (int j = 0; j < L_PER; j++) {
        sq += base[(long long)j * E3];
        sk += base[(long long)j * E3 + DIM];
    }
    ql[idx] = sq * (0.125f / 16.0f);   // fold in dh^-0.5 and mean
    kl[idx] = sk * (1.0f / 16.0f);
}

// ---------------------------------------------------------------------------
// Softmax over rows of 256 (warp per row, blockDim (32,8))
// ---------------------------------------------------------------------------
__global__ void softmax256_kernel(float* __restrict__ data, int rows) {
    int row = blockIdx.x * 8 + threadIdx.y;
    if (row >= rows) return;
    float4* p4 = (float4*)(data + (long long)row * 256);
    int lane = threadIdx.x;
    float4 u = p4[lane], v = p4[lane + 32];
    float mx = fmaxf(fmaxf(fmaxf(u.x, u.y), fmaxf(u.z, u.w)),
                     fmaxf(fmaxf(v.x, v.y), fmaxf(v.z, v.w)));
    #pragma unroll
    for (int o = 16; o; o >>= 1) mx = fmaxf(mx, __shfl_xor_sync(0xffffffffu, mx, o));
    u.x = expf(u.x - mx); u.y = expf(u.y - mx); u.z = expf(u.z - mx); u.w = expf(u.w - mx);
    v.x = expf(v.x - mx); v.y = expf(v.y - mx); v.z = expf(v.z - mx); v.w = expf(v.w - mx);
    float s = u.x + u.y + u.z + u.w + v.x + v.y + v.z + v.w;
    #pragma unroll
    for (int o = 16; o; o >>= 1) s += __shfl_xor_sync(0xffffffffu, s, o);
    float inv = 1.0f / s;
    u.x *= inv; u.y *= inv; u.z *= inv; u.w *= inv;
    v.x *= inv; v.y *= inv; v.z *= inv; v.w *= inv;
    p4[lane] = u; p4[lane + 32] = v;
}

// ---------------------------------------------------------------------------
// Softmax over rows of 4096 (block of 256 per row)
// ---------------------------------------------------------------------------
__global__ void softmax4096_kernel(float* __restrict__ data) {
    __shared__ float sm[32];
    float4* p4 = (float4*)(data + (long long)blockIdx.x * N_TOK);
    int t = threadIdx.x;
    float4 r[4];
    #pragma unroll
    for (int j = 0; j < 4; j++) r[j] = p4[t + j * 256];
    float mx = -FLT_MAX;
    #pragma unroll
    for (int j = 0; j < 4; j++)
        mx = fmaxf(mx, fmaxf(fmaxf(r[j].x, r[j].y), fmaxf(r[j].z, r[j].w)));
    mx = bredMax(mx, sm);
    float s = 0.f;
    #pragma unroll
    for (int j = 0; j < 4; j++) {
        r[j].x = expf(r[j].x - mx); r[j].y = expf(r[j].y - mx);
        r[j].z = expf(r[j].z - mx); r[j].w = expf(r[j].w - mx);
        s += r[j].x + r[j].y + r[j].z + r[j].w;
    }
    s = bredSum(s, sm);
    float inv = 1.0f / s;
    #pragma unroll
    for (int j = 0; j < 4; j++) {
        r[j].x *= inv; r[j].y *= inv; r[j].z *= inv; r[j].w *= inv;
        p4[t + j * 256] = r[j];
    }
}

// ---------------------------------------------------------------------------
// pinv init-scale: max row-abs-sum, max col-abs-sum (global scalars)
// ---------------------------------------------------------------------------
__global__ void reset_kernel(float* scal) {
    if (threadIdx.x < 2) scal[threadIdx.x] = 0.0f;
}

__global__ void pinv_reduce_kernel(const float* __restrict__ a2, float* __restrict__ scal) {
    int bh = blockIdx.x, j = threadIdx.x;
    const float* a = a2 + (long long)bh * (M_LM * M_LM);
    float cs = 0.f, rs = 0.f;
    for (int i = 0; i < M_LM; i++) {
        cs += fabsf(a[i * M_LM + j]);
        rs += fabsf(a[j * M_LM + i]);
    }
    atomicMax((int*)&scal[0], __float_as_int(rs));
    atomicMax((int*)&scal[1], __float_as_int(cs));
}

__global__ void zinit_kernel(const float* __restrict__ a2, float* __restrict__ z,
                             const float* __restrict__ scal) {
    float inv = 1.0f / (scal[0] * scal[1]);
    int idx = blockIdx.x * 256 + threadIdx.x;     // over 64*65536
    int bh = idx >> 16, r = (idx >> 8) & 255, c = idx & 255;
    z[idx] = a2[((long long)bh << 16) + (c << 8) + r] * inv;
}

__global__ void idminus_kernel(const float* __restrict__ in, float* __restrict__ out,
                               float alpha) {
    int idx = blockIdx.x * 256 + threadIdx.x;
    int r = (idx >> 8) & 255, c = idx & 255;
    out[idx] = ((r == c) ? alpha : 0.0f) - in[idx];
}

// ---------------------------------------------------------------------------
// Depthwise residual conv (33 taps over sequence) added into Y ([b,n,h*dh])
// ---------------------------------------------------------------------------
__global__ void conv_add_kernel(const float* __restrict__ qkv, const float* __restrict__ cw,
                                float* __restrict__ Y) {
    __shared__ float w[KER];
    int bh = blockIdx.y;
    int bb = bh >> 3, h = bh & 7;
    int tid = threadIdx.y * 64 + threadIdx.x;
    if (tid < KER) w[tid] = cw[h * KER + tid];
    __syncthreads();
    int j = threadIdx.x;
    int i = blockIdx.x * 4 + threadIdx.y;
    const float* vb = qkv + (long long)bb * N_TOK * E3 + 2 * DIM + h * DH + j;
    float acc = 0.f;
    #pragma unroll
    for (int t = 0; t < KER; t++) {
        int r = i + t - KER / 2;
        if (r >= 0 && r < N_TOK) acc += w[t] * vb[(long long)r * E3];
    }
    Y[((long long)(bb * N_TOK + i)) * DIM + h * DH + j] += acc;
}

// ---------------------------------------------------------------------------
// Final epilogue: out = x*omega + proj + bias   (proj already in out)
// ---------------------------------------------------------------------------
__global__ void final_ep_kernel(const float* __restrict__ x, const float* __restrict__ ob,
                                const float* __restrict__ omega, float* __restrict__ out) {
    long long idx = (long long)blockIdx.x * 256 + threadIdx.x;
    out[idx] = x[idx] * omega[0] + out[idx] + ob[idx & (DIM - 1)];
}

// ---------------------------------------------------------------------------
// Launcher
// ---------------------------------------------------------------------------
template <typename T>
static float* sym(T& s) {
    void* p = nullptr;
    cudaGetSymbolAddress(&p, s);
    return (float*)p;
}

extern "C" void kernel_launch(void* const* d_in, const int* in_sizes, int n_in,
                              void* d_out, int out_size) {
    const float* x      = (const float*)d_in[0];
    const float* ln_w   = (const float*)d_in[1];
    const float* ln_b   = (const float*)d_in[2];
    const float* qkv_w  = (const float*)d_in[3];
    const float* out_w  = (const float*)d_in[4];
    const float* out_b  = (const float*)d_in[5];
    const float* conv_w = (const float*)d_in[6];
    const float* omega  = (const float*)d_in[7];
    float* out = (float*)d_out;

    float* xn    = sym(g_xn);
    float* qkv   = sym(g_qkv);
    float* ql    = sym(g_ql);
    float* kl    = sym(g_kl);
    float* attn1 = sym(g_attn1);
    float* attn3 = sym(g_attn3);
    float* o1    = sym(g_o1);
    float* a2    = sym(g_a2);
    float* z     = sym(g_z);
    float* z2    = sym(g_z2);
    float* az    = sym(g_az);
    float* t1    = sym(g_t1);
    float* t2    = sym(g_t2);
    float* kv    = sym(g_kv);
    float* Y     = sym(g_y);
    float* scal  = sym(g_scal);

    const long long sA1 = (long long)N_TOK * M_LM;     // 1048576 (attn1/attn3/o1 per-bh)
    const long long sLM = (long long)M_LM * DH;        // 16384
    const long long sMM = (long long)M_LM * M_LM;      // 65536
    const long long sQB = (long long)N_TOK * E3;       // per-batch qkv stride

    // 1. LayerNorm
    ln_kernel<<<BN, 256>>>(x, ln_w, ln_b, xn);

    // 2. QKV projection: qkv[32768,1536] = xn @ qkv_w^T
    launch_gemm(true, xn, qkv_w, qkv, BN, E3, DIM, DIM, DIM, E3,
                0, 0, 0, 0, 0, 0, 1, 1, 1.0f);

    // 3. Landmark means (q scaled by dh^-0.5)
    landmark_kernel<<<(BHN * M_LM * DH) / 256, 256>>>(qkv, ql, kl);

    // 4. sim1 = scale * q @ k_l^T  -> attn1 [bh,4096,256]
    launch_gemm(true, qkv, kl, attn1, N_TOK, M_LM, DH, E3, DH, M_LM,
                sQB, DH, 8 * sLM, sLM, 8 * sA1, sA1, HEADS, BHN, 0.125f);
    softmax256_kernel<<<(BHN * N_TOK) / 8, dim3(32, 8)>>>(attn1, BHN * N_TOK);

    // 5. sim2 = q_l @ k_l^T -> a2 [bh,256,256]
    launch_gemm(true, ql, kl, a2, M_LM, M_LM, DH, DH, DH, M_LM,
                8 * sLM, sLM, 8 * sLM, sLM, 8 * sMM, sMM, HEADS, BHN, 1.0f);
    softmax256_kernel<<<(BHN * M_LM) / 8, dim3(32, 8)>>>(a2, BHN * M_LM);

    // 6. sim3 = q_l @ k^T -> attn3 [bh,256,4096]
    launch_gemm(true, ql, qkv + DIM, attn3, M_LM, N_TOK, DH, DH, E3, N_TOK,
                8 * sLM, sLM, sQB, DH, 8 * sA1, sA1, HEADS, BHN, 1.0f);
    softmax4096_kernel<<<BHN * M_LM, 256>>>(attn3);

    // 7. Moore-Penrose pinv of a2 (6 Newton-Schulz iterations)
    reset_kernel<<<1, 32>>>(scal);
    pinv_reduce_kernel<<<BHN, 256>>>(a2, scal);
    zinit_kernel<<<(BHN * (int)sMM) / 256, 256>>>(a2, z, scal);

    float* zc = z;
    float* zn = z2;
    const int eg = (BHN * (int)sMM) / 256;
    for (int it = 0; it < 6; it++) {
        launch_gemm(false, a2, zc, az, M_LM, M_LM, M_LM, M_LM, M_LM, M_LM,
                    sMM, 0, sMM, 0, sMM, 0, 1, BHN, 1.0f);
        idminus_kernel<<<eg, 256>>>(az, t1, 7.0f);
        launch_gemm(false, az, t1, t2, M_LM, M_LM, M_LM, M_LM, M_LM, M_LM,
                    sMM, 0, sMM, 0, sMM, 0, 1, BHN, 1.0f);
        idminus_kernel<<<eg, 256>>>(t2, t2, 15.0f);
        launch_gemm(false, az, t2, t1, M_LM, M_LM, M_LM, M_LM, M_LM, M_LM,
                    sMM, 0, sMM, 0, sMM, 0, 1, BHN, 1.0f);
        idminus_kernel<<<eg, 256>>>(t1, t1, 13.0f);
        launch_gemm(false, zc, t1, zn, M_LM, M_LM, M_LM, M_LM, M_LM, M_LM,
                    sMM, 0, sMM, 0, sMM, 0, 1, BHN, 0.25f);
        float* tmp = zc; zc = zn; zn = tmp;
    }
    // zc holds attn2_inv

    // 8. kv = attn3 @ v  -> [bh,256,64]
    launch_gemm(false, attn3, qkv + 2 * DIM, kv, M_LM, DH, N_TOK, N_TOK, E3, DH,
                8 * sA1, sA1, sQB, DH, 8 * sLM, sLM, HEADS, BHN, 1.0f);

    // 9. o1 = attn1 @ attn2_inv -> [bh,4096,256]
    launch_gemm(false, attn1, zc, o1, N_TOK, M_LM, M_LM, M_LM, M_LM, M_LM,
                8 * sA1, sA1, 8 * sMM, sMM, 8 * sA1, sA1, HEADS, BHN, 1.0f);

    // 10. Y[b,n,h*dh] = o1 @ kv (written directly in transposed layout)
    launch_gemm(false, o1, kv, Y, N_TOK, DH, M_LM, M_LM, DH, DIM,
                8 * sA1, sA1, 8 * sLM, sLM, (long long)N_TOK * DIM, DH,
                HEADS, BHN, 1.0f);

    // 11. += depthwise conv residual of v
    conv_add_kernel<<<dim3(N_TOK / 4, BHN), dim3(64, 4)>>>(qkv, conv_w, Y);

    // 12. out = Y @ out_w^T
    launch_gemm(true, Y, out_w, out, BN, DIM, DIM, DIM, DIM, DIM,
                0, 0, 0, 0, 0, 0, 1, 1, 1.0f);

    // 13. out = x*omega + out + out_b
    final_ep_kernel<<<(BN * DIM) / 256, 256>>>(x, out_b, omega, out);
}

// round 3
// speedup vs baseline: 1.2411x; 1.2411x over previous
#include <cuda_runtime.h>
#include <math.h>
#include <float.h>

#define B_SZ     8
#define N_TOK    4096
#define DIM      512
#define HEADS    8
#define DH       64
#define M_LM     256
#define L_PER    16
#define E3       1536
#define BN       (B_SZ * N_TOK)         // 32768
#define BHN      (B_SZ * HEADS)         // 64
#define KER      33

// ---------------------------------------------------------------------------
// Device scratch
// ---------------------------------------------------------------------------
__device__ __align__(256) float g_xn   [BN * DIM];
__device__ __align__(256) float g_qkv  [BN * E3];
__device__ __align__(256) float g_ql   [BHN * M_LM * DH];
__device__ __align__(256) float g_kl   [BHN * M_LM * DH];
__device__ __align__(256) float g_attn1[BHN * N_TOK * M_LM];
__device__ __align__(256) float g_attn3[BHN * M_LM * N_TOK];
__device__ __align__(256) float g_o1   [BHN * N_TOK * M_LM];
__device__ __align__(256) float g_a2   [BHN * M_LM * M_LM];
__device__ __align__(256) float g_z    [BHN * M_LM * M_LM];
__device__ __align__(256) float g_z2   [BHN * M_LM * M_LM];
__device__ __align__(256) float g_az   [BHN * M_LM * M_LM];
__device__ __align__(256) float g_t1   [BHN * M_LM * M_LM];
__device__ __align__(256) float g_t2   [BHN * M_LM * M_LM];
__device__ __align__(256) float g_kv   [BHN * M_LM * DH];
__device__ __align__(256) float g_y    [BN * DIM];
__device__ __align__(256) float g_scal [2];

// ---------------------------------------------------------------------------
// Block reductions
// ---------------------------------------------------------------------------
__device__ __forceinline__ float bredSum(float v, float* sm) {
    #pragma unroll
    for (int o = 16; o; o >>= 1) v += __shfl_xor_sync(0xffffffffu, v, o);
    int w = threadIdx.x >> 5, l = threadIdx.x & 31;
    if (l == 0) sm[w] = v;
    __syncthreads();
    if (w == 0) {
        v = (l < 8) ? sm[l] : 0.0f;
        #pragma unroll
        for (int o = 4; o; o >>= 1) v += __shfl_xor_sync(0xffffffffu, v, o);
        if (l == 0) sm[0] = v;
    }
    __syncthreads();
    v = sm[0];
    __syncthreads();
    return v;
}

__device__ __forceinline__ float bredMax(float v, float* sm) {
    #pragma unroll
    for (int o = 16; o; o >>= 1) v = fmaxf(v, __shfl_xor_sync(0xffffffffu, v, o));
    int w = threadIdx.x >> 5, l = threadIdx.x & 31;
    if (l == 0) sm[w] = v;
    __syncthreads();
    if (w == 0) {
        v = (l < 8) ? sm[l] : -FLT_MAX;
        #pragma unroll
        for (int o = 4; o; o >>= 1) v = fmaxf(v, __shfl_xor_sync(0xffffffffu, v, o));
        if (l == 0) sm[0] = v;
    }
    __syncthreads();
    v = sm[0];
    __syncthreads();
    return v;
}

// ---------------------------------------------------------------------------
// LayerNorm
// ---------------------------------------------------------------------------
__global__ void ln_kernel(const float* __restrict__ x, const float* __restrict__ w,
                          const float* __restrict__ bias, float* __restrict__ o) {
    __shared__ float sm[32];
    long long row = blockIdx.x;
    const float2* xr = (const float2*)(x + row * DIM);
    int t = threadIdx.x;
    float2 v = xr[t];
    float mu = bredSum(v.x + v.y, sm) * (1.0f / DIM);
    float d0 = v.x - mu, d1 = v.y - mu;
    float var = bredSum(d0 * d0 + d1 * d1, sm) * (1.0f / DIM);
    float rs = rsqrtf(var + 1e-5f);
    float2 wv = ((const float2*)w)[t];
    float2 bv = ((const float2*)bias)[t];
    float2* orow = (float2*)(o + row * DIM);
    orow[t] = make_float2(d0 * rs * wv.x + bv.x, d1 * rs * wv.y + bv.y);
}

// ---------------------------------------------------------------------------
// Big-tile GEMM: 128x128x16 tile, 8x8 per thread, 256 threads.
// C = diag*I + alpha * A (.) op(B). M,N mult 128; K mult 16.
// ---------------------------------------------------------------------------
template <bool TRANSB>
__global__ void __launch_bounds__(256, 2)
gemm128_kernel(const float* __restrict__ Amat, const float* __restrict__ Bmat,
               float* __restrict__ Cmat, int K, int lda, int ldb, int ldc,
               long long sAo, long long sAi, long long sBo, long long sBi,
               long long sCo, long long sCi, int Hdiv, float alpha, float diag) {
    __shared__ float As[16][132];
    __shared__ float Bs[16][132];
    int z = blockIdx.z;
    int zo = z / Hdiv, zi = z - zo * Hdiv;
    Amat += zo * sAo + zi * sAi;
    Bmat += zo * sBo + zi * sBi;
    Cmat += zo * sCo + zi * sCi;
    const int m0 = blockIdx.y * 128, n0 = blockIdx.x * 128;
    const int tid = threadIdx.x;
    const int lr = tid & 127;          // row within tile (A and B-trans loads)
    const int lk = (tid >> 7) << 3;    // 0 or 8
    const int br = tid >> 4;           // 0..15 (B non-trans loads)
    const int bc = (tid & 15) << 3;    // 0..120
    const int ty = tid >> 4, tx = tid & 15;

    const float* Ap = Amat + (long long)(m0 + lr) * lda + lk;
    const float* Bp = TRANSB ? (Bmat + (long long)(n0 + lr) * ldb + lk)
                             : (Bmat + (long long)br * ldb + n0 + bc);

    float4 a0 = *(const float4*)Ap;
    float4 a1 = *(const float4*)(Ap + 4);
    float4 b0 = *(const float4*)Bp;
    float4 b1 = *(const float4*)(Bp + 4);

    As[lk + 0][lr] = a0.x; As[lk + 1][lr] = a0.y; As[lk + 2][lr] = a0.z; As[lk + 3][lr] = a0.w;
    As[lk + 4][lr] = a1.x; As[lk + 5][lr] = a1.y; As[lk + 6][lr] = a1.z; As[lk + 7][lr] = a1.w;
    if (TRANSB) {
        Bs[lk + 0][lr] = b0.x; Bs[lk + 1][lr] = b0.y; Bs[lk + 2][lr] = b0.z; Bs[lk + 3][lr] = b0.w;
        Bs[lk + 4][lr] = b1.x; Bs[lk + 5][lr] = b1.y; Bs[lk + 6][lr] = b1.z; Bs[lk + 7][lr] = b1.w;
    } else {
        *(float4*)&Bs[br][bc] = b0;
        *(float4*)&Bs[br][bc + 4] = b1;
    }

    float acc[8][8] = {};
    const int ktiles = K >> 4;
    for (int kt = 1; ; kt++) {
        __syncthreads();
        bool more = kt < ktiles;
        float4 na0, na1, nb0, nb1;
        if (more) {
            Ap += 16;
            na0 = *(const float4*)Ap;
            na1 = *(const float4*)(Ap + 4);
            if (TRANSB) Bp += 16; else Bp += (long long)16 * ldb;
            nb0 = *(const float4*)Bp;
            nb1 = *(const float4*)(Bp + 4);
        }
        #pragma unroll
        for (int kk = 0; kk < 16; kk++) {
            float4 av0 = *(const float4*)&As[kk][ty << 2];
            float4 av1 = *(const float4*)&As[kk][64 + (ty << 2)];
            float4 bv0 = *(const float4*)&Bs[kk][tx << 2];
            float4 bv1 = *(const float4*)&Bs[kk][64 + (tx << 2)];
            float a[8] = {av0.x, av0.y, av0.z, av0.w, av1.x, av1.y, av1.z, av1.w};
            float b[8] = {bv0.x, bv0.y, bv0.z, bv0.w, bv1.x, bv1.y, bv1.z, bv1.w};
            #pragma unroll
            for (int i = 0; i < 8; i++)
                #pragma unroll
                for (int j = 0; j < 8; j++)
                    acc[i][j] = fmaf(a[i], b[j], acc[i][j]);
        }
        if (!more) break;
        __syncthreads();
        As[lk + 0][lr] = na0.x; As[lk + 1][lr] = na0.y; As[lk + 2][lr] = na0.z; As[lk + 3][lr] = na0.w;
        As[lk + 4][lr] = na1.x; As[lk + 5][lr] = na1.y; As[lk + 6][lr] = na1.z; As[lk + 7][lr] = na1.w;
        if (TRANSB) {
            Bs[lk + 0][lr] = nb0.x; Bs[lk + 1][lr] = nb0.y; Bs[lk + 2][lr] = nb0.z; Bs[lk + 3][lr] = nb0.w;
            Bs[lk + 4][lr] = nb1.x; Bs[lk + 5][lr] = nb1.y; Bs[lk + 6][lr] = nb1.z; Bs[lk + 7][lr] = nb1.w;
        } else {
            *(float4*)&Bs[br][bc] = nb0;
            *(float4*)&Bs[br][bc + 4] = nb1;
        }
    }

    #pragma unroll
    for (int ih = 0; ih < 2; ih++)
        #pragma unroll
        for (int ii = 0; ii < 4; ii++) {
            int mi = ih * 64 + (ty << 2) + ii;
            int gm = m0 + mi;
            long long crow = (long long)gm * ldc + n0;
            #pragma unroll
            for (int jh = 0; jh < 2; jh++) {
                int nj = jh * 64 + (tx << 2);
                int gn = n0 + nj;
                float4 o;
                o.x = alpha * acc[ih * 4 + ii][jh * 4 + 0] + ((gm == gn + 0) ? diag : 0.0f);
                o.y = alpha * acc[ih * 4 + ii][jh * 4 + 1] + ((gm == gn + 1) ? diag : 0.0f);
                o.z = alpha * acc[ih * 4 + ii][jh * 4 + 2] + ((gm == gn + 2) ? diag : 0.0f);
                o.w = alpha * acc[ih * 4 + ii][jh * 4 + 3] + ((gm == gn + 3) ? diag : 0.0f);
                *(float4*)(Cmat + crow + nj) = o;
            }
        }
}

static inline void launch_gemm128(bool transB, const float* Amat, const float* Bmat,
                                  float* Cmat, int M, int N, int K,
                                  int lda, int ldb, int ldc,
                                  long long sAo, long long sAi, long long sBo, long long sBi,
                                  long long sCo, long long sCi, int Hdiv, int batch,
                                  float alpha, float diag) {
    dim3 grid(N / 128, M / 128, batch), block(256);
    if (transB)
        gemm128_kernel<true><<<grid, block>>>(Amat, Bmat, Cmat, K, lda, ldb, ldc,
                                              sAo, sAi, sBo, sBi, sCo, sCi, Hdiv, alpha, diag);
    else
        gemm128_kernel<false><<<grid, block>>>(Amat, Bmat, Cmat, K, lda, ldb, ldc,
                                               sAo, sAi, sBo, sBi, sCo, sCi, Hdiv, alpha, diag);
}

// ---------------------------------------------------------------------------
// Small-tile GEMM (64x64x16, 4x4 per thread) — used for N=64 GEMMs only
// ---------------------------------------------------------------------------
template <bool TRANSB>
__global__ void __launch_bounds__(256)
gemm_kernel(const float* __restrict__ Amat, const float* __restrict__ Bmat,
            float* __restrict__ Cmat, int K, int lda, int ldb, int ldc,
            long long sAo, long long sAi, long long sBo, long long sBi,
            long long sCo, long long sCi, int Hdiv, float alpha) {
    __shared__ float As[16][64];
    __shared__ float Bs[16][64];
    int z = blockIdx.z;
    int zo = z / Hdiv, zi = z - zo * Hdiv;
    Amat += zo * sAo + zi * sAi;
    Bmat += zo * sBo + zi * sBi;
    Cmat += zo * sCo + zi * sCi;
    int m0 = blockIdx.y * 64, n0 = blockIdx.x * 64;
    int tid = threadIdx.x;
    int tx = tid & 15, ty = tid >> 4;
    int lrow = tid >> 2;
    int lk4  = (tid & 3) << 2;
    int brow = tid >> 4;
    int bcol = (tid & 15) << 2;

    float acc[4][4] = {};
    for (int k0 = 0; k0 < K; k0 += 16) {
        float4 a4 = *(const float4*)(Amat + (long long)(m0 + lrow) * lda + k0 + lk4);
        As[lk4 + 0][lrow] = a4.x; As[lk4 + 1][lrow] = a4.y;
        As[lk4 + 2][lrow] = a4.z; As[lk4 + 3][lrow] = a4.w;
        if (TRANSB) {
            float4 b4 = *(const float4*)(Bmat + (long long)(n0 + lrow) * ldb + k0 + lk4);
            Bs[lk4 + 0][lrow] = b4.x; Bs[lk4 + 1][lrow] = b4.y;
            Bs[lk4 + 2][lrow] = b4.z; Bs[lk4 + 3][lrow] = b4.w;
        } else {
            float4 b4 = *(const float4*)(Bmat + (long long)(k0 + brow) * ldb + n0 + bcol);
            *(float4*)&Bs[brow][bcol] = b4;
        }
        __syncthreads();
        #pragma unroll
        for (int kk = 0; kk < 16; kk++) {
            float4 av = *(const float4*)&As[kk][ty << 2];
            float4 bv = *(const float4*)&Bs[kk][tx << 2];
            float aa[4] = {av.x, av.y, av.z, av.w};
            float bb[4] = {bv.x, bv.y, bv.z, bv.w};
            #pragma unroll
            for (int i = 0; i < 4; i++)
                #pragma unroll
                for (int j = 0; j < 4; j++)
                    acc[i][j] += aa[i] * bb[j];
        }
        __syncthreads();
    }
    #pragma unroll
    for (int i = 0; i < 4; i++) {
        float4 o;
        o.x = acc[i][0] * alpha; o.y = acc[i][1] * alpha;
        o.z = acc[i][2] * alpha; o.w = acc[i][3] * alpha;
        *(float4*)(Cmat + (long long)(m0 + (ty << 2) + i) * ldc + n0 + (tx << 2)) = o;
    }
}

static inline void launch_gemm(bool transB, const float* Amat, const float* Bmat,
                               float* Cmat, int M, int N, int K,
                               int lda, int ldb, int ldc,
                               long long sAo, long long sAi, long long sBo, long long sBi,
                               long long sCo, long long sCi, int Hdiv, int batch,
                               float alpha) {
    dim3 grid(N / 64, M / 64, batch), block(256);
    if (transB)
        gemm_kernel<true><<<grid, block>>>(Amat, Bmat, Cmat, K, lda, ldb, ldc,
                                           sAo, sAi, sBo, sBi, sCo, sCi, Hdiv, alpha);
    else
        gemm_kernel<false><<<grid, block>>>(Amat, Bmat, Cmat, K, lda, ldb, ldc,
                                            sAo, sAi, sBo, sBi, sCo, sCi, Hdiv, alpha);
}

// ---------------------------------------------------------------------------
// Landmark means
// ---------------------------------------------------------------------------
__global__ void landmark_kernel(const float* __restrict__ qkv,
                                float* __restrict__ ql, float* __restrict__ kl) {
    int idx = blockIdx.x * 256 + threadIdx.x;
    int d  = idx & 63;
    int mi = (idx >> 6) & 255;
    int bh = idx >> 14;
    int bb = bh >> 3, h = bh & 7;
    const float* base = qkv + ((long long)(bb * N_TOK + mi * L_PER)) * E3 + h * DH + d;
    float sq = 0.f, sk = 0.f;
    #pragma unroll
    for (int j = 0; j < L_PER; j++) {
        sq += base[(long long)j * E3];
        sk += base[(long long)j * E3 + DIM];
    }
    ql[idx] = sq * (0.125f / 16.0f);
    kl[idx] = sk * (1.0f / 16.0f);
}

// ---------------------------------------------------------------------------
// Softmax kernels
// ---------------------------------------------------------------------------
__global__ void softmax256_kernel(float* __restrict__ data, int rows) {
    int row = blockIdx.x * 8 + threadIdx.y;
    if (row >= rows) return;
    float4* p4 = (float4*)(data + (long long)row * 256);
    int lane = threadIdx.x;
    float4 u = p4[lane], v = p4[lane + 32];
    float mx = fmaxf(fmaxf(fmaxf(u.x, u.y), fmaxf(u.z, u.w)),
                     fmaxf(fmaxf(v.x, v.y), fmaxf(v.z, v.w)));
    #pragma unroll
    for (int o = 16; o; o >>= 1) mx = fmaxf(mx, __shfl_xor_sync(0xffffffffu, mx, o));
    u.x = expf(u.x - mx); u.y = expf(u.y - mx); u.z = expf(u.z - mx); u.w = expf(u.w - mx);
    v.x = expf(v.x - mx); v.y = expf(v.y - mx); v.z = expf(v.z - mx); v.w = expf(v.w - mx);
    float s = u.x + u.y + u.z + u.w + v.x + v.y + v.z + v.w;
    #pragma unroll
    for (int o = 16; o; o >>= 1) s += __shfl_xor_sync(0xffffffffu, s, o);
    float inv = 1.0f / s;
    u.x *= inv; u.y *= inv; u.z *= inv; u.w *= inv;
    v.x *= inv; v.y *= inv; v.z *= inv; v.w *= inv;
    p4[lane] = u; p4[lane + 32] = v;
}

__global__ void softmax4096_kernel(float* __restrict__ data) {
    __shared__ float sm[32];
    float4* p4 = (float4*)(data + (long long)blockIdx.x * N_TOK);
    int t = threadIdx.x;
    float4 r[4];
    #pragma unroll
    for (int j = 0; j < 4; j++) r[j] = p4[t + j * 256];
    float mx = -FLT_MAX;
    #pragma unroll
    for (int j = 0; j < 4; j++)
        mx = fmaxf(mx, fmaxf(fmaxf(r[j].x, r[j].y), fmaxf(r[j].z, r[j].w)));
    mx = bredMax(mx, sm);
    float s = 0.f;
    #pragma unroll
    for (int j = 0; j < 4; j++) {
        r[j].x = expf(r[j].x - mx); r[j].y = expf(r[j].y - mx);
        r[j].z = expf(r[j].z - mx); r[j].w = expf(r[j].w - mx);
        s += r[j].x + r[j].y + r[j].z + r[j].w;
    }
    s = bredSum(s, sm);
    float inv = 1.0f / s;
    #pragma unroll
    for (int j = 0; j < 4; j++) {
        r[j].x *= inv; r[j].y *= inv; r[j].z *= inv; r[j].w *= inv;
        p4[t + j * 256] = r[j];
    }
}

// ---------------------------------------------------------------------------
// pinv helpers
// ---------------------------------------------------------------------------
__global__ void reset_kernel(float* scal) {
    if (threadIdx.x < 2) scal[threadIdx.x] = 0.0f;
}

__global__ void pinv_reduce_kernel(const float* __restrict__ a2, float* __restrict__ scal) {
    int bh = blockIdx.x, j = threadIdx.x;
    const float* a = a2 + (long long)bh * (M_LM * M_LM);
    float cs = 0.f, rs = 0.f;
    for (int i = 0; i < M_LM; i++) {
        cs += fabsf(a[i * M_LM + j]);
        rs += fabsf(a[j * M_LM + i]);
    }
    atomicMax((int*)&scal[0], __float_as_int(rs));
    atomicMax((int*)&scal[1], __float_as_int(cs));
}

__global__ void zinit_kernel(const float* __restrict__ a2, float* __restrict__ z,
                             const float* __restrict__ scal) {
    float inv = 1.0f / (scal[0] * scal[1]);
    int idx = blockIdx.x * 256 + threadIdx.x;
    int bh = idx >> 16, r = (idx >> 8) & 255, c = idx & 255;
    z[idx] = a2[((long long)bh << 16) + (c << 8) + r] * inv;
}

__global__ void idminus_kernel(const float* __restrict__ in, float* __restrict__ out,
                               float alpha) {
    int idx = blockIdx.x * 256 + threadIdx.x;
    int r = (idx >> 8) & 255, c = idx & 255;
    out[idx] = ((r == c) ? alpha : 0.0f) - in[idx];
}

// ---------------------------------------------------------------------------
// Depthwise residual conv
// ---------------------------------------------------------------------------
__global__ void conv_add_kernel(const float* __restrict__ qkv, const float* __restrict__ cw,
                                float* __restrict__ Y) {
    __shared__ float w[KER];
    int bh = blockIdx.y;
    int bb = bh >> 3, h = bh & 7;
    int tid = threadIdx.y * 64 + threadIdx.x;
    if (tid < KER) w[tid] = cw[h * KER + tid];
    __syncthreads();
    int j = threadIdx.x;
    int i = blockIdx.x * 4 + threadIdx.y;
    const float* vb = qkv + (long long)bb * N_TOK * E3 + 2 * DIM + h * DH + j;
    float acc = 0.f;
    #pragma unroll
    for (int t = 0; t < KER; t++) {
        int r = i + t - KER / 2;
        if (r >= 0 && r < N_TOK) acc += w[t] * vb[(long long)r * E3];
    }
    Y[((long long)(bb * N_TOK + i)) * DIM + h * DH + j] += acc;
}

// ---------------------------------------------------------------------------
// Final epilogue
// ---------------------------------------------------------------------------
__global__ void final_ep_kernel(const float* __restrict__ x, const float* __restrict__ ob,
                                const float* __restrict__ omega, float* __restrict__ out) {
    long long idx = (long long)blockIdx.x * 256 + threadIdx.x;
    out[idx] = x[idx] * omega[0] + out[idx] + ob[idx & (DIM - 1)];
}

// ---------------------------------------------------------------------------
// Launcher
// ---------------------------------------------------------------------------
template <typename T>
static float* sym(T& s) {
    void* p = nullptr;
    cudaGetSymbolAddress(&p, s);
    return (float*)p;
}

extern "C" void kernel_launch(void* const* d_in, const int* in_sizes, int n_in,
                              void* d_out, int out_size) {
    const float* x      = (const float*)d_in[0];
    const float* ln_w   = (const float*)d_in[1];
    const float* ln_b   = (const float*)d_in[2];
    const float* qkv_w  = (const float*)d_in[3];
    const float* out_w  = (const float*)d_in[4];
    const float* out_b  = (const float*)d_in[5];
    const float* conv_w = (const float*)d_in[6];
    const float* omega  = (const float*)d_in[7];
    float* out = (float*)d_out;

    float* xn    = sym(g_xn);
    float* qkv   = sym(g_qkv);
    float* ql    = sym(g_ql);
    float* kl    = sym(g_kl);
    float* attn1 = sym(g_attn1);
    float* attn3 = sym(g_attn3);
    float* o1    = sym(g_o1);
    float* a2    = sym(g_a2);
    float* z     = sym(g_z);
    float* z2    = sym(g_z2);
    float* az    = sym(g_az);
    float* t1    = sym(g_t1);
    float* t2    = sym(g_t2);
    float* kv    = sym(g_kv);
    float* Y     = sym(g_y);
    float* scal  = sym(g_scal);

    const long long sA1 = (long long)N_TOK * M_LM;
    const long long sLM = (long long)M_LM * DH;
    const long long sMM = (long long)M_LM * M_LM;
    const long long sQB = (long long)N_TOK * E3;

    // 1. LayerNorm
    ln_kernel<<<BN, 256>>>(x, ln_w, ln_b, xn);

    // 2. QKV projection
    launch_gemm128(true, xn, qkv_w, qkv, BN, E3, DIM, DIM, DIM, E3,
                   0, 0, 0, 0, 0, 0, 1, 1, 1.0f, 0.0f);

    // 3. Landmark means
    landmark_kernel<<<(BHN * M_LM * DH) / 256, 256>>>(qkv, ql, kl);

    // 4. sim1 -> softmax -> attn1 [bh,4096,256]
    launch_gemm128(true, qkv, kl, attn1, N_TOK, M_LM, DH, E3, DH, M_LM,
                   sQB, DH, 8 * sLM, sLM, 8 * sA1, sA1, HEADS, BHN, 0.125f, 0.0f);
    softmax256_kernel<<<(BHN * N_TOK) / 8, dim3(32, 8)>>>(attn1, BHN * N_TOK);

    // 5. sim2 -> softmax -> a2 [bh,256,256]
    launch_gemm128(true, ql, kl, a2, M_LM, M_LM, DH, DH, DH, M_LM,
                   8 * sLM, sLM, 8 * sLM, sLM, 8 * sMM, sMM, HEADS, BHN, 1.0f, 0.0f);
    softmax256_kernel<<<(BHN * M_LM) / 8, dim3(32, 8)>>>(a2, BHN * M_LM);

    // 6. sim3 -> softmax -> attn3 [bh,256,4096]
    launch_gemm128(true, ql, qkv + DIM, attn3, M_LM, N_TOK, DH, DH, E3, N_TOK,
                   8 * sLM, sLM, sQB, DH, 8 * sA1, sA1, HEADS, BHN, 1.0f, 0.0f);
    softmax4096_kernel<<<BHN * M_LM, 256>>>(attn3);

    // 7. pinv (6 Newton-Schulz iterations, idminus fused into 2 of 4 GEMMs)
    reset_kernel<<<1, 32>>>(scal);
    pinv_reduce_kernel<<<BHN, 256>>>(a2, scal);
    zinit_kernel<<<(BHN * (int)sMM) / 256, 256>>>(a2, z, scal);

    float* zc = z;
    float* zn = z2;
    const int eg = (BHN * (int)sMM) / 256;
    for (int it = 0; it < 6; it++) {
        launch_gemm128(false, a2, zc, az, M_LM, M_LM, M_LM, M_LM, M_LM, M_LM,
                       sMM, 0, sMM, 0, sMM, 0, 1, BHN, 1.0f, 0.0f);
        idminus_kernel<<<eg, 256>>>(az, t1, 7.0f);
        // t2 = 15I - az@t1
        launch_gemm128(false, az, t1, t2, M_LM, M_LM, M_LM, M_LM, M_LM, M_LM,
                       sMM, 0, sMM, 0, sMM, 0, 1, BHN, -1.0f, 15.0f);
        // t1 = 13I - az@t2
        launch_gemm128(false, az, t2, t1, M_LM, M_LM, M_LM, M_LM, M_LM, M_LM,
                       sMM, 0, sMM, 0, sMM, 0, 1, BHN, -1.0f, 13.0f);
        // zn = 0.25 * zc@t1
        launch_gemm128(false, zc, t1, zn, M_LM, M_LM, M_LM, M_LM, M_LM, M_LM,
                       sMM, 0, sMM, 0, sMM, 0, 1, BHN, 0.25f, 0.0f);
        float* tmp = zc; zc = zn; zn = tmp;
    }

    // 8. kv = attn3 @ v  (N=64 -> small tile)
    launch_gemm(false, attn3, qkv + 2 * DIM, kv, M_LM, DH, N_TOK, N_TOK, E3, DH,
                8 * sA1, sA1, sQB, DH, 8 * sLM, sLM, HEADS, BHN, 1.0f);

    // 9. o1 = attn1 @ attn2_inv
    launch_gemm128(false, attn1, zc, o1, N_TOK, M_LM, M_LM, M_LM, M_LM, M_LM,
                   8 * sA1, sA1, 8 * sMM, sMM, 8 * sA1, sA1, HEADS, BHN, 1.0f, 0.0f);

    // 10. Y = o1 @ kv  (N=64 -> small tile, written in [b,n,h*dh] layout)
    launch_gemm(false, o1, kv, Y, N_TOK, DH, M_LM, M_LM, DH, DIM,
                8 * sA1, sA1, 8 * sLM, sLM, (long long)N_TOK * DIM, DH,
                HEADS, BHN, 1.0f);

    // 11. conv residual
    conv_add_kernel<<<dim3(N_TOK / 4, BHN), dim3(64, 4)>>>(qkv, conv_w, Y);

    // 12. out projection
    launch_gemm128(true, Y, out_w, out, BN, DIM, DIM, DIM, DIM, DIM,
                   0, 0, 0, 0, 0, 0, 1, 1, 1.0f, 0.0f);

    // 13. final residual
    final_ep_kernel<<<(BN * DIM) / 256, 256>>>(x, out_b, omega, out);
}

// round 5
// speedup vs baseline: 1.7959x; 1.4470x over previous
#include <cuda_runtime.h>
#include <stdint.h>
#include <math.h>
#include <float.h>

#define B_SZ     8
#define N_TOK    4096
#define DIM      512
#define HEADS    8
#define DH       64
#define M_LM     256
#define L_PER    16
#define E3       1536
#define BN       (B_SZ * N_TOK)         // 32768
#define BHN      (B_SZ * HEADS)         // 64
#define KER      33

// ---------------------------------------------------------------------------
// Device scratch
// ---------------------------------------------------------------------------
__device__ __align__(256) float g_xn   [BN * DIM];
__device__ __align__(256) float g_qkv  [BN * E3];
__device__ __align__(256) float g_ql   [BHN * M_LM * DH];
__device__ __align__(256) float g_kl   [BHN * M_LM * DH];
__device__ __align__(256) float g_attn1[BHN * N_TOK * M_LM];
__device__ __align__(256) float g_attn3[BHN * M_LM * N_TOK];
__device__ __align__(256) float g_o1   [BHN * N_TOK * M_LM];
__device__ __align__(256) float g_a2   [BHN * M_LM * M_LM];
__device__ __align__(256) float g_z    [BHN * M_LM * M_LM];
__device__ __align__(256) float g_z2   [BHN * M_LM * M_LM];
__device__ __align__(256) float g_az   [BHN * M_LM * M_LM];
__device__ __align__(256) float g_t1   [BHN * M_LM * M_LM];
__device__ __align__(256) float g_t2   [BHN * M_LM * M_LM];
__device__ __align__(256) float g_kv   [BHN * M_LM * DH];
__device__ __align__(256) float g_y    [BN * DIM];
__device__ __align__(256) float g_scal [2];

// ---------------------------------------------------------------------------
// Helpers
// ---------------------------------------------------------------------------
__device__ __forceinline__ uint32_t f2tf32(float f) {
    uint32_t r;
    asm("cvt.rna.tf32.f32 %0, %1;" : "=r"(r) : "f"(f));
    return r;
}

__device__ __forceinline__ float bredSum(float v, float* sm) {
    #pragma unroll
    for (int o = 16; o; o >>= 1) v += __shfl_xor_sync(0xffffffffu, v, o);
    int w = threadIdx.x >> 5, l = threadIdx.x & 31;
    if (l == 0) sm[w] = v;
    __syncthreads();
    if (w == 0) {
        v = (l < 8) ? sm[l] : 0.0f;
        #pragma unroll
        for (int o = 4; o; o >>= 1) v += __shfl_xor_sync(0xffffffffu, v, o);
        if (l == 0) sm[0] = v;
    }
    __syncthreads();
    v = sm[0];
    __syncthreads();
    return v;
}

__device__ __forceinline__ float bredMax(float v, float* sm) {
    #pragma unroll
    for (int o = 16; o; o >>= 1) v = fmaxf(v, __shfl_xor_sync(0xffffffffu, v, o));
    int w = threadIdx.x >> 5, l = threadIdx.x & 31;
    if (l == 0) sm[w] = v;
    __syncthreads();
    if (w == 0) {
        v = (l < 8) ? sm[l] : -FLT_MAX;
        #pragma unroll
        for (int o = 4; o; o >>= 1) v = fmaxf(v, __shfl_xor_sync(0xffffffffu, v, o));
        if (l == 0) sm[0] = v;
    }
    __syncthreads();
    v = sm[0];
    __syncthreads();
    return v;
}

// ---------------------------------------------------------------------------
// LayerNorm
// ---------------------------------------------------------------------------
__global__ void ln_kernel(const float* __restrict__ x, const float* __restrict__ w,
                          const float* __restrict__ bias, float* __restrict__ o) {
    __shared__ float sm[32];
    long long row = blockIdx.x;
    const float2* xr = (const float2*)(x + row * DIM);
    int t = threadIdx.x;
    float2 v = xr[t];
    float mu = bredSum(v.x + v.y, sm) * (1.0f / DIM);
    float d0 = v.x - mu, d1 = v.y - mu;
    float var = bredSum(d0 * d0 + d1 * d1, sm) * (1.0f / DIM);
    float rs = rsqrtf(var + 1e-5f);
    float2 wv = ((const float2*)w)[t];
    float2 bv = ((const float2*)bias)[t];
    float2* orow = (float2*)(o + row * DIM);
    orow[t] = make_float2(d0 * rs * wv.x + bv.x, d1 * rs * wv.y + bv.y);
}

// ---------------------------------------------------------------------------
// TF32 tensor-core GEMM.
// Tile: 128 x (4*WN) x 16. 8 warps arranged 2(m) x 4(n); warp tile 64 x WN.
// mma.sync m16n8k8 tf32. C = diag*I + alpha * A (.) op(B).
// M mult 128, N mult 4*WN, K mult 16.
// ---------------------------------------------------------------------------
template <bool TRANSB, int WN>
__global__ void __launch_bounds__(256)
tgemm_kernel(const float* __restrict__ Amat, const float* __restrict__ Bmat,
             float* __restrict__ Cmat, int K, int lda, int ldb, int ldc,
             long long sAo, long long sAi, long long sBo, long long sBi,
             long long sCo, long long sCi, int Hdiv, float alpha, float diag) {
    constexpr int BNT  = WN * 4;              // 128 or 64
    constexpr int NT   = WN / 8;              // n-tiles per warp (4 or 2)
    constexpr int BSTR = (BNT == 128) ? 136 : 72;   // stride ≡ 8 (mod 32)

    __shared__ uint32_t As[16][136];
    __shared__ uint32_t Bs[16][BSTR];

    int z = blockIdx.z;
    int zo = z / Hdiv, zi = z - zo * Hdiv;
    Amat += zo * sAo + zi * sAi;
    Bmat += zo * sBo + zi * sBi;
    Cmat += zo * sCo + zi * sCi;

    const int m0 = blockIdx.y * 128, n0 = blockIdx.x * BNT;
    const int tid  = threadIdx.x;
    const int lane = tid & 31;
    const int warp = tid >> 5;
    const int wm = warp & 1;                  // 0..1
    const int wn = warp >> 1;                 // 0..3
    const int g  = lane >> 2;                 // 0..7
    const int t4 = lane & 3;                  // 0..3

    // ---- global load indexing ----
    const int alr = tid & 127;                // A row in tile
    const int alk = (tid >> 7) << 3;          // A k-offset 0/8
    const float* Ap = Amat + (long long)(m0 + alr) * lda + alk;

    int blr = 0, blk = 0, bbr = 0, bbc = 0;
    const float* Bp;
    bool bact = true;
    if (TRANSB) {
        if (BNT == 128) { blr = tid & 127; blk = (tid >> 7) << 3; }
        else            { blr = tid & 63;  blk = ((tid >> 6) & 1) << 3; bact = tid < 128; }
        Bp = Bmat + (long long)(n0 + blr) * ldb + blk;
    } else {
        if (BNT == 128) { bbr = tid >> 4;       bbc = (tid & 15) << 3; }
        else            { bbr = (tid >> 3) & 15; bbc = (tid & 7) << 3; bact = tid < 128; }
        Bp = Bmat + (long long)bbr * ldb + n0 + bbc;
    }

    float4 pa0 = *(const float4*)Ap;
    float4 pa1 = *(const float4*)(Ap + 4);
    float4 pb0 = {}, pb1 = {};
    if (bact) { pb0 = *(const float4*)Bp; pb1 = *(const float4*)(Bp + 4); }

    // initial smem store
    {
        As[alk + 0][alr] = f2tf32(pa0.x); As[alk + 1][alr] = f2tf32(pa0.y);
        As[alk + 2][alr] = f2tf32(pa0.z); As[alk + 3][alr] = f2tf32(pa0.w);
        As[alk + 4][alr] = f2tf32(pa1.x); As[alk + 5][alr] = f2tf32(pa1.y);
        As[alk + 6][alr] = f2tf32(pa1.z); As[alk + 7][alr] = f2tf32(pa1.w);
        if (bact) {
            if (TRANSB) {
                Bs[blk + 0][blr] = f2tf32(pb0.x); Bs[blk + 1][blr] = f2tf32(pb0.y);
                Bs[blk + 2][blr] = f2tf32(pb0.z); Bs[blk + 3][blr] = f2tf32(pb0.w);
                Bs[blk + 4][blr] = f2tf32(pb1.x); Bs[blk + 5][blr] = f2tf32(pb1.y);
                Bs[blk + 6][blr] = f2tf32(pb1.z); Bs[blk + 7][blr] = f2tf32(pb1.w);
            } else {
                Bs[bbr][bbc + 0] = f2tf32(pb0.x); Bs[bbr][bbc + 1] = f2tf32(pb0.y);
                Bs[bbr][bbc + 2] = f2tf32(pb0.z); Bs[bbr][bbc + 3] = f2tf32(pb0.w);
                Bs[bbr][bbc + 4] = f2tf32(pb1.x); Bs[bbr][bbc + 5] = f2tf32(pb1.y);
                Bs[bbr][bbc + 6] = f2tf32(pb1.z); Bs[bbr][bbc + 7] = f2tf32(pb1.w);
            }
        }
    }

    float acc[4][NT][4];
    #pragma unroll
    for (int a = 0; a < 4; a++)
        #pragma unroll
        for (int b = 0; b < NT; b++)
            #pragma unroll
            for (int c = 0; c < 4; c++) acc[a][b][c] = 0.0f;

    const int ktiles = K >> 4;
    for (int kt = 1; ; kt++) {
        __syncthreads();
        bool more = kt < ktiles;
        if (more) {
            Ap += 16;
            pa0 = *(const float4*)Ap;
            pa1 = *(const float4*)(Ap + 4);
            if (TRANSB) Bp += 16; else Bp += (long long)16 * ldb;
            if (bact) { pb0 = *(const float4*)Bp; pb1 = *(const float4*)(Bp + 4); }
        }
        #pragma unroll
        for (int ks = 0; ks < 16; ks += 8) {
            uint32_t af[4][4];
            #pragma unroll
            for (int mt = 0; mt < 4; mt++) {
                int mr = wm * 64 + mt * 16 + g;
                af[mt][0] = As[ks + t4][mr];
                af[mt][1] = As[ks + t4][mr + 8];
                af[mt][2] = As[ks + t4 + 4][mr];
                af[mt][3] = As[ks + t4 + 4][mr + 8];
            }
            #pragma unroll
            for (int nt = 0; nt < NT; nt++) {
                uint32_t b0 = Bs[ks + t4][wn * WN + nt * 8 + g];
                uint32_t b1 = Bs[ks + t4 + 4][wn * WN + nt * 8 + g];
                #pragma unroll
                for (int mt = 0; mt < 4; mt++) {
                    asm volatile(
                        "mma.sync.aligned.m16n8k8.row.col.f32.tf32.tf32.f32 "
                        "{%0,%1,%2,%3}, {%4,%5,%6,%7}, {%8,%9}, {%0,%1,%2,%3};"
                        : "+f"(acc[mt][nt][0]), "+f"(acc[mt][nt][1]),
                          "+f"(acc[mt][nt][2]), "+f"(acc[mt][nt][3])
                        : "r"(af[mt][0]), "r"(af[mt][1]), "r"(af[mt][2]), "r"(af[mt][3]),
                          "r"(b0), "r"(b1));
                }
            }
        }
        if (!more) break;
        __syncthreads();
        As[alk + 0][alr] = f2tf32(pa0.x); As[alk + 1][alr] = f2tf32(pa0.y);
        As[alk + 2][alr] = f2tf32(pa0.z); As[alk + 3][alr] = f2tf32(pa0.w);
        As[alk + 4][alr] = f2tf32(pa1.x); As[alk + 5][alr] = f2tf32(pa1.y);
        As[alk + 6][alr] = f2tf32(pa1.z); As[alk + 7][alr] = f2tf32(pa1.w);
        if (bact) {
            if (TRANSB) {
                Bs[blk + 0][blr] = f2tf32(pb0.x); Bs[blk + 1][blr] = f2tf32(pb0.y);
                Bs[blk + 2][blr] = f2tf32(pb0.z); Bs[blk + 3][blr] = f2tf32(pb0.w);
                Bs[blk + 4][blr] = f2tf32(pb1.x); Bs[blk + 5][blr] = f2tf32(pb1.y);
                Bs[blk + 6][blr] = f2tf32(pb1.z); Bs[blk + 7][blr] = f2tf32(pb1.w);
            } else {
                Bs[bbr][bbc + 0] = f2tf32(pb0.x); Bs[bbr][bbc + 1] = f2tf32(pb0.y);
                Bs[bbr][bbc + 2] = f2tf32(pb0.z); Bs[bbr][bbc + 3] = f2tf32(pb0.w);
                Bs[bbr][bbc + 4] = f2tf32(pb1.x); Bs[bbr][bbc + 5] = f2tf32(pb1.y);
                Bs[bbr][bbc + 6] = f2tf32(pb1.z); Bs[bbr][bbc + 7] = f2tf32(pb1.w);
            }
        }
    }

    // epilogue
    #pragma unroll
    for (int mt = 0; mt < 4; mt++) {
        int r0 = m0 + wm * 64 + mt * 16 + g;
        #pragma unroll
        for (int nt = 0; nt < NT; nt++) {
            int c0 = n0 + wn * WN + nt * 8 + (t4 << 1);
            float2 v0, v1;
            v0.x = alpha * acc[mt][nt][0] + ((r0 == c0)     ? diag : 0.0f);
            v0.y = alpha * acc[mt][nt][1] + ((r0 == c0 + 1) ? diag : 0.0f);
            v1.x = alpha * acc[mt][nt][2] + ((r0 + 8 == c0)     ? diag : 0.0f);
            v1.y = alpha * acc[mt][nt][3] + ((r0 + 8 == c0 + 1) ? diag : 0.0f);
            *(float2*)(Cmat + (long long)r0 * ldc + c0) = v0;
            *(float2*)(Cmat + (long long)(r0 + 8) * ldc + c0) = v1;
        }
    }
}

static inline void launch_t128(bool transB, const float* A, const float* Bm, float* C,
                               int M, int N, int K, int lda, int ldb, int ldc,
                               long long sAo, long long sAi, long long sBo, long long sBi,
                               long long sCo, long long sCi, int Hdiv, int batch,
                               float alpha, float diag) {
    dim3 grid(N / 128, M / 128, batch), block(256);
    if (transB)
        tgemm_kernel<true, 32><<<grid, block>>>(A, Bm, C, K, lda, ldb, ldc,
                                                sAo, sAi, sBo, sBi, sCo, sCi, Hdiv, alpha, diag);
    else
        tgemm_kernel<false, 32><<<grid, block>>>(A, Bm, C, K, lda, ldb, ldc,
                                                 sAo, sAi, sBo, sBi, sCo, sCi, Hdiv, alpha, diag);
}

static inline void launch_t64(bool transB, const float* A, const float* Bm, float* C,
                              int M, int N, int K, int lda, int ldb, int ldc,
                              long long sAo, long long sAi, long long sBo, long long sBi,
                              long long sCo, long long sCi, int Hdiv, int batch,
                              float alpha, float diag) {
    dim3 grid(N / 64, M / 128, batch), block(256);
    if (transB)
        tgemm_kernel<true, 16><<<grid, block>>>(A, Bm, C, K, lda, ldb, ldc,
                                                sAo, sAi, sBo, sBi, sCo, sCi, Hdiv, alpha, diag);
    else
        tgemm_kernel<false, 16><<<grid, block>>>(A, Bm, C, K, lda, ldb, ldc,
                                                 sAo, sAi, sBo, sBi, sCo, sCi, Hdiv, alpha, diag);
}

// ---------------------------------------------------------------------------
// Landmark means
// ---------------------------------------------------------------------------
__global__ void landmark_kernel(const float* __restrict__ qkv,
                                float* __restrict__ ql, float* __restrict__ kl) {
    int idx = blockIdx.x * 256 + threadIdx.x;
    int d  = idx & 63;
    int mi = (idx >> 6) & 255;
    int bh = idx >> 14;
    int bb = bh >> 3, h = bh & 7;
    const float* base = qkv + ((long long)(bb * N_TOK + mi * L_PER)) * E3 + h * DH + d;
    float sq = 0.f, sk = 0.f;
    #pragma unroll
    for (int j = 0; j < L_PER; j++) {
        sq += base[(long long)j * E3];
        sk += base[(long long)j * E3 + DIM];
    }
    ql[idx] = sq * (0.125f / 16.0f);
    kl[idx] = sk * (1.0f / 16.0f);
}

// ---------------------------------------------------------------------------
// Softmax kernels
// ---------------------------------------------------------------------------
__global__ void softmax256_kernel(float* __restrict__ data, int rows) {
    int row = blockIdx.x * 8 + threadIdx.y;
    if (row >= rows) return;
    float4* p4 = (float4*)(data + (long long)row * 256);
    int lane = threadIdx.x;
    float4 u = p4[lane], v = p4[lane + 32];
    float mx = fmaxf(fmaxf(fmaxf(u.x, u.y), fmaxf(u.z, u.w)),
                     fmaxf(fmaxf(v.x, v.y), fmaxf(v.z, v.w)));
    #pragma unroll
    for (int o = 16; o; o >>= 1) mx = fmaxf(mx, __shfl_xor_sync(0xffffffffu, mx, o));
    u.x = expf(u.x - mx); u.y = expf(u.y - mx); u.z = expf(u.z - mx); u.w = expf(u.w - mx);
    v.x = expf(v.x - mx); v.y = expf(v.y - mx); v.z = expf(v.z - mx); v.w = expf(v.w - mx);
    float s = u.x + u.y + u.z + u.w + v.x + v.y + v.z + v.w;
    #pragma unroll
    for (int o = 16; o; o >>= 1) s += __shfl_xor_sync(0xffffffffu, s, o);
    float inv = 1.0f / s;
    u.x *= inv; u.y *= inv; u.z *= inv; u.w *= inv;
    v.x *= inv; v.y *= inv; v.z *= inv; v.w *= inv;
    p4[lane] = u; p4[lane + 32] = v;
}

__global__ void softmax4096_kernel(float* __restrict__ data) {
    __shared__ float sm[32];
    float4* p4 = (float4*)(data + (long long)blockIdx.x * N_TOK);
    int t = threadIdx.x;
    float4 r[4];
    #pragma unroll
    for (int j = 0; j < 4; j++) r[j] = p4[t + j * 256];
    float mx = -FLT_MAX;
    #pragma unroll
    for (int j = 0; j < 4; j++)
        mx = fmaxf(mx, fmaxf(fmaxf(r[j].x, r[j].y), fmaxf(r[j].z, r[j].w)));
    mx = bredMax(mx, sm);
    float s = 0.f;
    #pragma unroll
    for (int j = 0; j < 4; j++) {
        r[j].x = expf(r[j].x - mx); r[j].y = expf(r[j].y - mx);
        r[j].z = expf(r[j].z - mx); r[j].w = expf(r[j].w - mx);
        s += r[j].x + r[j].y + r[j].z + r[j].w;
    }
    s = bredSum(s, sm);
    float inv = 1.0f / s;
    #pragma unroll
    for (int j = 0; j < 4; j++) {
        r[j].x *= inv; r[j].y *= inv; r[j].z *= inv; r[j].w *= inv;
        p4[t + j * 256] = r[j];
    }
}

// ---------------------------------------------------------------------------
// pinv helpers
// ---------------------------------------------------------------------------
__global__ void reset_kernel(float* scal) {
    if (threadIdx.x < 2) scal[threadIdx.x] = 0.0f;
}

__global__ void pinv_reduce_kernel(const float* __restrict__ a2, float* __restrict__ scal) {
    int bh = blockIdx.x, j = threadIdx.x;
    const float* a = a2 + (long long)bh * (M_LM * M_LM);
    float cs = 0.f, rs = 0.f;
    for (int i = 0; i < M_LM; i++) {
        cs += fabsf(a[i * M_LM + j]);
        rs += fabsf(a[j * M_LM + i]);
    }
    atomicMax((int*)&scal[0], __float_as_int(rs));
    atomicMax((int*)&scal[1], __float_as_int(cs));
}

__global__ void zinit_kernel(const float* __restrict__ a2, float* __restrict__ z,
                             const float* __restrict__ scal) {
    float inv = 1.0f / (scal[0] * scal[1]);
    int idx = blockIdx.x * 256 + threadIdx.x;
    int bh = idx >> 16, r = (idx >> 8) & 255, c = idx & 255;
    z[idx] = a2[((long long)bh << 16) + (c << 8) + r] * inv;
}

__global__ void idminus_kernel(const float* __restrict__ in, float* __restrict__ out,
                               float alpha) {
    int idx = blockIdx.x * 256 + threadIdx.x;
    int r = (idx >> 8) & 255, c = idx & 255;
    out[idx] = ((r == c) ? alpha : 0.0f) - in[idx];
}

// ---------------------------------------------------------------------------
// Depthwise residual conv
// ---------------------------------------------------------------------------
__global__ void conv_add_kernel(const float* __restrict__ qkv, const float* __restrict__ cw,
                                float* __restrict__ Y) {
    __shared__ float w[KER];
    int bh = blockIdx.y;
    int bb = bh >> 3, h = bh & 7;
    int tid = threadIdx.y * 64 + threadIdx.x;
    if (tid < KER) w[tid] = cw[h * KER + tid];
    __syncthreads();
    int j = threadIdx.x;
    int i = blockIdx.x * 4 + threadIdx.y;
    const float* vb = qkv + (long long)bb * N_TOK * E3 + 2 * DIM + h * DH + j;
    float acc = 0.f;
    #pragma unroll
    for (int t = 0; t < KER; t++) {
        int r = i + t - KER / 2;
        if (r >= 0 && r < N_TOK) acc += w[t] * vb[(long long)r * E3];
    }
    Y[((long long)(bb * N_TOK + i)) * DIM + h * DH + j] += acc;
}

// ---------------------------------------------------------------------------
// Final epilogue
// ---------------------------------------------------------------------------
__global__ void final_ep_kernel(const float* __restrict__ x, const float* __restrict__ ob,
                                const float* __restrict__ omega, float* __restrict__ out) {
    long long idx = (long long)blockIdx.x * 256 + threadIdx.x;
    out[idx] = x[idx] * omega[0] + out[idx] + ob[idx & (DIM - 1)];
}

// ---------------------------------------------------------------------------
// Launcher
// ---------------------------------------------------------------------------
template <typename T>
static float* sym(T& s) {
    void* p = nullptr;
    cudaGetSymbolAddress(&p, s);
    return (float*)p;
}

extern "C" void kernel_launch(void* const* d_in, const int* in_sizes, int n_in,
                              void* d_out, int out_size) {
    const float* x      = (const float*)d_in[0];
    const float* ln_w   = (const float*)d_in[1];
    const float* ln_b   = (const float*)d_in[2];
    const float* qkv_w  = (const float*)d_in[3];
    const float* out_w  = (const float*)d_in[4];
    const float* out_b  = (const float*)d_in[5];
    const float* conv_w = (const float*)d_in[6];
    const float* omega  = (const float*)d_in[7];
    float* out = (float*)d_out;

    float* xn    = sym(g_xn);
    float* qkv   = sym(g_qkv);
    float* ql    = sym(g_ql);
    float* kl    = sym(g_kl);
    float* attn1 = sym(g_attn1);
    float* attn3 = sym(g_attn3);
    float* o1    = sym(g_o1);
    float* a2    = sym(g_a2);
    float* z     = sym(g_z);
    float* z2    = sym(g_z2);
    float* az    = sym(g_az);
    float* t1    = sym(g_t1);
    float* t2    = sym(g_t2);
    float* kv    = sym(g_kv);
    float* Y     = sym(g_y);
    float* scal  = sym(g_scal);

    const long long sA1 = (long long)N_TOK * M_LM;
    const long long sLM = (long long)M_LM * DH;
    const long long sMM = (long long)M_LM * M_LM;
    const long long sQB = (long long)N_TOK * E3;

    // 1. LayerNorm
    ln_kernel<<<BN, 256>>>(x, ln_w, ln_b, xn);

    // 2. QKV projection
    launch_t128(true, xn, qkv_w, qkv, BN, E3, DIM, DIM, DIM, E3,
                0, 0, 0, 0, 0, 0, 1, 1, 1.0f, 0.0f);

    // 3. Landmark means
    landmark_kernel<<<(BHN * M_LM * DH) / 256, 256>>>(qkv, ql, kl);

    // 4. sim1 -> softmax -> attn1 [bh,4096,256]
    launch_t128(true, qkv, kl, attn1, N_TOK, M_LM, DH, E3, DH, M_LM,
                sQB, DH, 8 * sLM, sLM, 8 * sA1, sA1, HEADS, BHN, 0.125f, 0.0f);
    softmax256_kernel<<<(BHN * N_TOK) / 8, dim3(32, 8)>>>(attn1, BHN * N_TOK);

    // 5. sim2 -> softmax -> a2 [bh,256,256]
    launch_t128(true, ql, kl, a2, M_LM, M_LM, DH, DH, DH, M_LM,
                8 * sLM, sLM, 8 * sLM, sLM, 8 * sMM, sMM, HEADS, BHN, 1.0f, 0.0f);
    softmax256_kernel<<<(BHN * M_LM) / 8, dim3(32, 8)>>>(a2, BHN * M_LM);

    // 6. sim3 -> softmax -> attn3 [bh,256,4096]
    launch_t128(true, ql, qkv + DIM, attn3, M_LM, N_TOK, DH, DH, E3, N_TOK,
                8 * sLM, sLM, sQB, DH, 8 * sA1, sA1, HEADS, BHN, 1.0f, 0.0f);
    softmax4096_kernel<<<BHN * M_LM, 256>>>(attn3);

    // 7. pinv (6 Newton-Schulz iterations)
    reset_kernel<<<1, 32>>>(scal);
    pinv_reduce_kernel<<<BHN, 256>>>(a2, scal);
    zinit_kernel<<<(BHN * (int)sMM) / 256, 256>>>(a2, z, scal);

    float* zc = z;
    float* zn = z2;
    const int eg = (BHN * (int)sMM) / 256;
    for (int it = 0; it < 6; it++) {
        launch_t128(false, a2, zc, az, M_LM, M_LM, M_LM, M_LM, M_LM, M_LM,
                    sMM, 0, sMM, 0, sMM, 0, 1, BHN, 1.0f, 0.0f);
        idminus_kernel<<<eg, 256>>>(az, t1, 7.0f);
        // t2 = 15I - az@t1
        launch_t128(false, az, t1, t2, M_LM, M_LM, M_LM, M_LM, M_LM, M_LM,
                    sMM, 0, sMM, 0, sMM, 0, 1, BHN, -1.0f, 15.0f);
        // t1 = 13I - az@t2
        launch_t128(false, az, t2, t1, M_LM, M_LM, M_LM, M_LM, M_LM, M_LM,
                    sMM, 0, sMM, 0, sMM, 0, 1, BHN, -1.0f, 13.0f);
        // zn = 0.25 * zc@t1
        launch_t128(false, zc, t1, zn, M_LM, M_LM, M_LM, M_LM, M_LM, M_LM,
                    sMM, 0, sMM, 0, sMM, 0, 1, BHN, 0.25f, 0.0f);
        float* tmp = zc; zc = zn; zn = tmp;
    }

    // 8. kv = attn3 @ v  (N=64)
    launch_t64(false, attn3, qkv + 2 * DIM, kv, M_LM, DH, N_TOK, N_TOK, E3, DH,
               8 * sA1, sA1, sQB, DH, 8 * sLM, sLM, HEADS, BHN, 1.0f, 0.0f);

    // 9. o1 = attn1 @ attn2_inv
    launch_t128(false, attn1, zc, o1, N_TOK, M_LM, M_LM, M_LM, M_LM, M_LM,
                8 * sA1, sA1, 8 * sMM, sMM, 8 * sA1, sA1, HEADS, BHN, 1.0f, 0.0f);

    // 10. Y = o1 @ kv  (N=64, written in [b,n,h*dh] layout)
    launch_t64(false, o1, kv, Y, N_TOK, DH, M_LM, M_LM, DH, DIM,
               8 * sA1, sA1, 8 * sLM, sLM, (long long)N_TOK * DIM, DH,
               HEADS, BHN, 1.0f, 0.0f);

    // 11. conv residual
    conv_add_kernel<<<dim3(N_TOK / 4, BHN), dim3(64, 4)>>>(qkv, conv_w, Y);

    // 12. out projection
    launch_t128(true, Y, out_w, out, BN, DIM, DIM, DIM, DIM, DIM,
                0, 0, 0, 0, 0, 0, 1, 1, 1.0f, 0.0f);

    // 13. final residual
    final_ep_kernel<<<(BN * DIM) / 256, 256>>>(x, out_b, omega, out);
}

// round 7
// speedup vs baseline: 2.2734x; 1.2659x over previous
#include <cuda_runtime.h>
#include <stdint.h>
#include <math.h>
#include <float.h>

#define B_SZ     8
#define N_TOK    4096
#define DIM      512
#define HEADS    8
#define DH       64
#define M_LM     256
#define L_PER    16
#define E3       1536
#define BN       (B_SZ * N_TOK)         // 32768
#define BHN      (B_SZ * HEADS)         // 64
#define KER      33

// ---------------------------------------------------------------------------
// Device scratch
// ---------------------------------------------------------------------------
__device__ __align__(256) float g_xn   [BN * DIM];
__device__ __align__(256) float g_qkv  [BN * E3];
__device__ __align__(256) float g_ql   [BHN * M_LM * DH];
__device__ __align__(256) float g_kl   [BHN * M_LM * DH];
__device__ __align__(256) float g_attn1[BHN * N_TOK * M_LM];
__device__ __align__(256) float g_attn3[BHN * M_LM * N_TOK];
__device__ __align__(256) float g_o1   [BHN * N_TOK * M_LM];
__device__ __align__(256) float g_a2   [BHN * M_LM * M_LM];
__device__ __align__(256) float g_z    [BHN * M_LM * M_LM];
__device__ __align__(256) float g_z2   [BHN * M_LM * M_LM];
__device__ __align__(256) float g_az   [BHN * M_LM * M_LM];
__device__ __align__(256) float g_t1   [BHN * M_LM * M_LM];
__device__ __align__(256) float g_t2   [BHN * M_LM * M_LM];
__device__ __align__(256) float g_kv   [BHN * M_LM * DH];
__device__ __align__(256) float g_y    [BN * DIM];
__device__ __align__(256) float g_scal [2];

// ---------------------------------------------------------------------------
// Helpers
// ---------------------------------------------------------------------------
__device__ __forceinline__ uint32_t packbf(float lo, float hi) {
    uint32_t r;
    asm("cvt.rn.bf16x2.f32 %0, %1, %2;" : "=r"(r) : "f"(hi), "f"(lo));
    return r;
}

__device__ __forceinline__ float bredSum(float v, float* sm) {
    #pragma unroll
    for (int o = 16; o; o >>= 1) v += __shfl_xor_sync(0xffffffffu, v, o);
    int w = threadIdx.x >> 5, l = threadIdx.x & 31;
    if (l == 0) sm[w] = v;
    __syncthreads();
    if (w == 0) {
        v = (l < 8) ? sm[l] : 0.0f;
        #pragma unroll
        for (int o = 4; o; o >>= 1) v += __shfl_xor_sync(0xffffffffu, v, o);
        if (l == 0) sm[0] = v;
    }
    __syncthreads();
    v = sm[0];
    __syncthreads();
    return v;
}

__device__ __forceinline__ float bredMax(float v, float* sm) {
    #pragma unroll
    for (int o = 16; o; o >>= 1) v = fmaxf(v, __shfl_xor_sync(0xffffffffu, v, o));
    int w = threadIdx.x >> 5, l = threadIdx.x & 31;
    if (l == 0) sm[w] = v;
    __syncthreads();
    if (w == 0) {
        v = (l < 8) ? sm[l] : -FLT_MAX;
        #pragma unroll
        for (int o = 4; o; o >>= 1) v = fmaxf(v, __shfl_xor_sync(0xffffffffu, v, o));
        if (l == 0) sm[0] = v;
    }
    __syncthreads();
    v = sm[0];
    __syncthreads();
    return v;
}

// ---------------------------------------------------------------------------
// LayerNorm
// ---------------------------------------------------------------------------
__global__ void ln_kernel(const float* __restrict__ x, const float* __restrict__ w,
                          const float* __restrict__ bias, float* __restrict__ o) {
    __shared__ float sm[32];
    long long row = blockIdx.x;
    const float2* xr = (const float2*)(x + row * DIM);
    int t = threadIdx.x;
    float2 v = xr[t];
    float mu = bredSum(v.x + v.y, sm) * (1.0f / DIM);
    float d0 = v.x - mu, d1 = v.y - mu;
    float var = bredSum(d0 * d0 + d1 * d1, sm) * (1.0f / DIM);
    float rs = rsqrtf(var + 1e-5f);
    float2 wv = ((const float2*)w)[t];
    float2 bv = ((const float2*)bias)[t];
    float2* orow = (float2*)(o + row * DIM);
    orow[t] = make_float2(d0 * rs * wv.x + bv.x, d1 * rs * wv.y + bv.y);
}

// ---------------------------------------------------------------------------
// BF16 tensor-core GEMM (fp32 accumulate).
// Tile: 128 x (4*WN) x 16. 8 warps 2(m) x 4(n); warp tile 64 x WN.
// mma.sync m16n8k16 bf16. Double-buffered smem, packed bf16x2 along k.
// C = diag*I + alpha * A (.) op(B).  M mult 128, N mult 4*WN, K mult 16.
// ---------------------------------------------------------------------------
template <bool TRANSB, int WN>
__global__ void __launch_bounds__(256)
tgemm_kernel(const float* __restrict__ Amat, const float* __restrict__ Bmat,
             float* __restrict__ Cmat, int K, int lda, int ldb, int ldc,
             long long sAo, long long sAi, long long sBo, long long sBi,
             long long sCo, long long sCi, int Hdiv, float alpha, float diag) {
    constexpr int BNT   = WN * 4;             // 128 or 64
    constexpr int NT    = WN / 8;             // 4 or 2
    constexpr int BSTR  = BNT + 8;            // ≡ 8 (mod 32) -> conflict-free frags
    constexpr int NPERT = BNT / 32;           // cols per thread in non-trans loader

    __shared__ uint32_t As[2][8][136];
    __shared__ uint32_t Bs[2][8][BSTR];

    int z = blockIdx.z;
    int zo = z / Hdiv, zi = z - zo * Hdiv;
    Amat += zo * sAo + zi * sAi;
    Bmat += zo * sBo + zi * sBi;
    Cmat += zo * sCo + zi * sCi;

    const int m0 = blockIdx.y * 128, n0 = blockIdx.x * BNT;
    const int tid  = threadIdx.x;
    const int lane = tid & 31;
    const int warp = tid >> 5;
    const int wm = warp & 1;
    const int wn = warp >> 1;
    const int g  = lane >> 2;
    const int t4 = lane & 3;

    // ---- A loader indexing: 128 rows x 2 k-halves ----
    const int alr = tid & 127;
    const int ak2 = ((tid >> 7) << 2);        // pair-index base: 0 or 4
    const float* Ap = Amat + (long long)(m0 + alr) * lda + (ak2 << 1);

    // ---- B loader indexing ----
    int blr = 0, bk2 = 0, br2 = 0, bcb = 0;
    const float* Bp;
    bool bact = true;
    if (TRANSB) {
        if (BNT == 128) { blr = tid & 127; bk2 = ((tid >> 7) << 2); }
        else            { blr = tid & 63;  bk2 = (((tid >> 6) & 1) << 2); bact = tid < 128; }
        Bp = Bmat + (long long)(n0 + blr) * ldb + (bk2 << 1);
    } else {
        br2 = tid >> 5;                       // 0..7 (k-pair row)
        bcb = (lane) * NPERT;                 // column base
        Bp = Bmat + (long long)(2 * br2) * ldb + n0 + bcb;
    }

    // ---- prologue: load + store tile 0 ----
    float4 pa0 = *(const float4*)Ap;
    float4 pa1 = *(const float4*)(Ap + 4);
    float4 pb0 = {}, pb1 = {};
    if (TRANSB) {
        if (bact) { pb0 = *(const float4*)Bp; pb1 = *(const float4*)(Bp + 4); }
    } else {
        if (NPERT == 4) {
            pb0 = *(const float4*)Bp;
            pb1 = *(const float4*)(Bp + ldb);
        } else {
            float2 u = *(const float2*)Bp;
            float2 v = *(const float2*)(Bp + ldb);
            pb0.x = u.x; pb0.y = u.y; pb1.x = v.x; pb1.y = v.y;
        }
    }

    {
        As[0][ak2 + 0][alr] = packbf(pa0.x, pa0.y);
        As[0][ak2 + 1][alr] = packbf(pa0.z, pa0.w);
        As[0][ak2 + 2][alr] = packbf(pa1.x, pa1.y);
        As[0][ak2 + 3][alr] = packbf(pa1.z, pa1.w);
        if (TRANSB) {
            if (bact) {
                Bs[0][bk2 + 0][blr] = packbf(pb0.x, pb0.y);
                Bs[0][bk2 + 1][blr] = packbf(pb0.z, pb0.w);
                Bs[0][bk2 + 2][blr] = packbf(pb1.x, pb1.y);
                Bs[0][bk2 + 3][blr] = packbf(pb1.z, pb1.w);
            }
        } else {
            Bs[0][br2][bcb + 0] = packbf(pb0.x, pb1.x);
            Bs[0][br2][bcb + 1] = packbf(pb0.y, pb1.y);
            if (NPERT == 4) {
                Bs[0][br2][bcb + 2] = packbf(pb0.z, pb1.z);
                Bs[0][br2][bcb + 3] = packbf(pb0.w, pb1.w);
            }
        }
    }
    __syncthreads();

    float acc[4][NT][4];
    #pragma unroll
    for (int a = 0; a < 4; a++)
        #pragma unroll
        for (int b = 0; b < NT; b++)
            #pragma unroll
            for (int c = 0; c < 4; c++) acc[a][b][c] = 0.0f;

    const int ktiles = K >> 4;
    int buf = 0;
    for (int kt = 0; kt < ktiles; kt++) {
        bool more = (kt + 1) < ktiles;
        if (more) {
            Ap += 16;
            pa0 = *(const float4*)Ap;
            pa1 = *(const float4*)(Ap + 4);
            if (TRANSB) {
                Bp += 16;
                if (bact) { pb0 = *(const float4*)Bp; pb1 = *(const float4*)(Bp + 4); }
            } else {
                Bp += (long long)16 * ldb;
                if (NPERT == 4) {
                    pb0 = *(const float4*)Bp;
                    pb1 = *(const float4*)(Bp + ldb);
                } else {
                    float2 u = *(const float2*)Bp;
                    float2 v = *(const float2*)(Bp + ldb);
                    pb0.x = u.x; pb0.y = u.y; pb1.x = v.x; pb1.y = v.y;
                }
            }
        }

        // ---- compute on current buffer ----
        uint32_t af[4][4];
        #pragma unroll
        for (int mt = 0; mt < 4; mt++) {
            int mr = wm * 64 + mt * 16 + g;
            af[mt][0] = As[buf][t4][mr];
            af[mt][1] = As[buf][t4][mr + 8];
            af[mt][2] = As[buf][t4 + 4][mr];
            af[mt][3] = As[buf][t4 + 4][mr + 8];
        }
        #pragma unroll
        for (int nt = 0; nt < NT; nt++) {
            uint32_t b0 = Bs[buf][t4][wn * WN + nt * 8 + g];
            uint32_t b1 = Bs[buf][t4 + 4][wn * WN + nt * 8 + g];
            #pragma unroll
            for (int mt = 0; mt < 4; mt++) {
                asm volatile(
                    "mma.sync.aligned.m16n8k16.row.col.f32.bf16.bf16.f32 "
                    "{%0,%1,%2,%3}, {%4,%5,%6,%7}, {%8,%9}, {%0,%1,%2,%3};"
                    : "+f"(acc[mt][nt][0]), "+f"(acc[mt][nt][1]),
                      "+f"(acc[mt][nt][2]), "+f"(acc[mt][nt][3])
                    : "r"(af[mt][0]), "r"(af[mt][1]), "r"(af[mt][2]), "r"(af[mt][3]),
                      "r"(b0), "r"(b1));
            }
        }

        if (more) {
            int nb = buf ^ 1;
            As[nb][ak2 + 0][alr] = packbf(pa0.x, pa0.y);
            As[nb][ak2 + 1][alr] = packbf(pa0.z, pa0.w);
            As[nb][ak2 + 2][alr] = packbf(pa1.x, pa1.y);
            As[nb][ak2 + 3][alr] = packbf(pa1.z, pa1.w);
            if (TRANSB) {
                if (bact) {
                    Bs[nb][bk2 + 0][blr] = packbf(pb0.x, pb0.y);
                    Bs[nb][bk2 + 1][blr] = packbf(pb0.z, pb0.w);
                    Bs[nb][bk2 + 2][blr] = packbf(pb1.x, pb1.y);
                    Bs[nb][bk2 + 3][blr] = packbf(pb1.z, pb1.w);
                }
            } else {
                Bs[nb][br2][bcb + 0] = packbf(pb0.x, pb1.x);
                Bs[nb][br2][bcb + 1] = packbf(pb0.y, pb1.y);
                if (NPERT == 4) {
                    Bs[nb][br2][bcb + 2] = packbf(pb0.z, pb1.z);
                    Bs[nb][br2][bcb + 3] = packbf(pb0.w, pb1.w);
                }
            }
            __syncthreads();
            buf = nb;
        }
    }

    // ---- epilogue ----
    #pragma unroll
    for (int mt = 0; mt < 4; mt++) {
        int r0 = m0 + wm * 64 + mt * 16 + g;
        #pragma unroll
        for (int nt = 0; nt < NT; nt++) {
            int c0 = n0 + wn * WN + nt * 8 + (t4 << 1);
            float2 v0, v1;
            v0.x = alpha * acc[mt][nt][0] + ((r0 == c0)     ? diag : 0.0f);
            v0.y = alpha * acc[mt][nt][1] + ((r0 == c0 + 1) ? diag : 0.0f);
            v1.x = alpha * acc[mt][nt][2] + ((r0 + 8 == c0)     ? diag : 0.0f);
            v1.y = alpha * acc[mt][nt][3] + ((r0 + 8 == c0 + 1) ? diag : 0.0f);
            *(float2*)(Cmat + (long long)r0 * ldc + c0) = v0;
            *(float2*)(Cmat + (long long)(r0 + 8) * ldc + c0) = v1;
        }
    }
}

static inline void launch_t128(bool transB, const float* A, const float* Bm, float* C,
                               int M, int N, int K, int lda, int ldb, int ldc,
                               long long sAo, long long sAi, long long sBo, long long sBi,
                               long long sCo, long long sCi, int Hdiv, int batch,
                               float alpha, float diag) {
    dim3 grid(N / 128, M / 128, batch), block(256);
    if (transB)
        tgemm_kernel<true, 32><<<grid, block>>>(A, Bm, C, K, lda, ldb, ldc,
                                                sAo, sAi, sBo, sBi, sCo, sCi, Hdiv, alpha, diag);
    else
        tgemm_kernel<false, 32><<<grid, block>>>(A, Bm, C, K, lda, ldb, ldc,
                                                 sAo, sAi, sBo, sBi, sCo, sCi, Hdiv, alpha, diag);
}

static inline void launch_t64(bool transB, const float* A, const float* Bm, float* C,
                              int M, int N, int K, int lda, int ldb, int ldc,
                              long long sAo, long long sAi, long long sBo, long long sBi,
                              long long sCo, long long sCi, int Hdiv, int batch,
                              float alpha, float diag) {
    dim3 grid(N / 64, M / 128, batch), block(256);
    if (transB)
        tgemm_kernel<true, 16><<<grid, block>>>(A, Bm, C, K, lda, ldb, ldc,
                                                sAo, sAi, sBo, sBi, sCo, sCi, Hdiv, alpha, diag);
    else
        tgemm_kernel<false, 16><<<grid, block>>>(A, Bm, C, K, lda, ldb, ldc,
                                                 sAo, sAi, sBo, sBi, sCo, sCi, Hdiv, alpha, diag);
}

// ---------------------------------------------------------------------------
// Landmark means
// ---------------------------------------------------------------------------
__global__ void landmark_kernel(const float* __restrict__ qkv,
                                float* __restrict__ ql, float* __restrict__ kl) {
    int idx = blockIdx.x * 256 + threadIdx.x;
    int d  = idx & 63;
    int mi = (idx >> 6) & 255;
    int bh = idx >> 14;
    int bb = bh >> 3, h = bh & 7;
    const float* base = qkv + ((long long)(bb * N_TOK + mi * L_PER)) * E3 + h * DH + d;
    float sq = 0.f, sk = 0.f;
    #pragma unroll
    for (int j = 0; j < L_PER; j++) {
        sq += base[(long long)j * E3];
        sk += base[(long long)j * E3 + DIM];
    }
    ql[idx] = sq * (0.125f / 16.0f);
    kl[idx] = sk * (1.0f / 16.0f);
}

// ---------------------------------------------------------------------------
// Softmax kernels
// ---------------------------------------------------------------------------
__global__ void softmax256_kernel(float* __restrict__ data, int rows) {
    int row = blockIdx.x * 8 + threadIdx.y;
    if (row >= rows) return;
    float4* p4 = (float4*)(data + (long long)row * 256);
    int lane = threadIdx.x;
    float4 u = p4[lane], v = p4[lane + 32];
    float mx = fmaxf(fmaxf(fmaxf(u.x, u.y), fmaxf(u.z, u.w)),
                     fmaxf(fmaxf(v.x, v.y), fmaxf(v.z, v.w)));
    #pragma unroll
    for (int o = 16; o; o >>= 1) mx = fmaxf(mx, __shfl_xor_sync(0xffffffffu, mx, o));
    u.x = expf(u.x - mx); u.y = expf(u.y - mx); u.z = expf(u.z - mx); u.w = expf(u.w - mx);
    v.x = expf(v.x - mx); v.y = expf(v.y - mx); v.z = expf(v.z - mx); v.w = expf(v.w - mx);
    float s = u.x + u.y + u.z + u.w + v.x + v.y + v.z + v.w;
    #pragma unroll
    for (int o = 16; o; o >>= 1) s += __shfl_xor_sync(0xffffffffu, s, o);
    float inv = 1.0f / s;
    u.x *= inv; u.y *= inv; u.z *= inv; u.w *= inv;
    v.x *= inv; v.y *= inv; v.z *= inv; v.w *= inv;
    p4[lane] = u; p4[lane + 32] = v;
}

__global__ void softmax4096_kernel(float* __restrict__ data) {
    __shared__ float sm[32];
    float4* p4 = (float4*)(data + (long long)blockIdx.x * N_TOK);
    int t = threadIdx.x;
    float4 r[4];
    #pragma unroll
    for (int j = 0; j < 4; j++) r[j] = p4[t + j * 256];
    float mx = -FLT_MAX;
    #pragma unroll
    for (int j = 0; j < 4; j++)
        mx = fmaxf(mx, fmaxf(fmaxf(r[j].x, r[j].y), fmaxf(r[j].z, r[j].w)));
    mx = bredMax(mx, sm);
    float s = 0.f;
    #pragma unroll
    for (int j = 0; j < 4; j++) {
        r[j].x = expf(r[j].x - mx); r[j].y = expf(r[j].y - mx);
        r[j].z = expf(r[j].z - mx); r[j].w = expf(r[j].w - mx);
        s += r[j].x + r[j].y + r[j].z + r[j].w;
    }
    s = bredSum(s, sm);
    float inv = 1.0f / s;
    #pragma unroll
    for (int j = 0; j < 4; j++) {
        r[j].x *= inv; r[j].y *= inv; r[j].z *= inv; r[j].w *= inv;
        p4[t + j * 256] = r[j];
    }
}

// ---------------------------------------------------------------------------
// pinv helpers
// ---------------------------------------------------------------------------
__global__ void reset_kernel(float* scal) {
    if (threadIdx.x < 2) scal[threadIdx.x] = 0.0f;
}

__global__ void pinv_reduce_kernel(const float* __restrict__ a2, float* __restrict__ scal) {
    int bh = blockIdx.x, j = threadIdx.x;
    const float* a = a2 + (long long)bh * (M_LM * M_LM);
    float cs = 0.f, rs = 0.f;
    for (int i = 0; i < M_LM; i++) {
        cs += fabsf(a[i * M_LM + j]);
        rs += fabsf(a[j * M_LM + i]);
    }
    atomicMax((int*)&scal[0], __float_as_int(rs));
    atomicMax((int*)&scal[1], __float_as_int(cs));
}

__global__ void zinit_kernel(const float* __restrict__ a2, float* __restrict__ z,
                             const float* __restrict__ scal) {
    float inv = 1.0f / (scal[0] * scal[1]);
    int idx = blockIdx.x * 256 + threadIdx.x;
    int bh = idx >> 16, r = (idx >> 8) & 255, c = idx & 255;
    z[idx] = a2[((long long)bh << 16) + (c << 8) + r] * inv;
}

__global__ void idminus_kernel(const float* __restrict__ in, float* __restrict__ out,
                               float alpha) {
    int idx = blockIdx.x * 256 + threadIdx.x;
    int r = (idx >> 8) & 255, c = idx & 255;
    out[idx] = ((r == c) ? alpha : 0.0f) - in[idx];
}

// ---------------------------------------------------------------------------
// Depthwise residual conv
// ---------------------------------------------------------------------------
__global__ void conv_add_kernel(const float* __restrict__ qkv, const float* __restrict__ cw,
                                float* __restrict__ Y) {
    __shared__ float w[KER];
    int bh = blockIdx.y;
    int bb = bh >> 3, h = bh & 7;
    int tid = threadIdx.y * 64 + threadIdx.x;
    if (tid < KER) w[tid] = cw[h * KER + tid];
    __syncthreads();
    int j = threadIdx.x;
    int i = blockIdx.x * 4 + threadIdx.y;
    const float* vb = qkv + (long long)bb * N_TOK * E3 + 2 * DIM + h * DH + j;
    float acc = 0.f;
    #pragma unroll
    for (int t = 0; t < KER; t++) {
        int r = i + t - KER / 2;
        if (r >= 0 && r < N_TOK) acc += w[t] * vb[(long long)r * E3];
    }
    Y[((long long)(bb * N_TOK + i)) * DIM + h * DH + j] += acc;
}

// ---------------------------------------------------------------------------
// Final epilogue
// ---------------------------------------------------------------------------
__global__ void final_ep_kernel(const float* __restrict__ x, const float* __restrict__ ob,
                                const float* __restrict__ omega, float* __restrict__ out) {
    long long idx = (long long)blockIdx.x * 256 + threadIdx.x;
    out[idx] = x[idx] * omega[0] + out[idx] + ob[idx & (DIM - 1)];
}

// ---------------------------------------------------------------------------
// Launcher
// ---------------------------------------------------------------------------
template <typename T>
static float* sym(T& s) {
    void* p = nullptr;
    cudaGetSymbolAddress(&p, s);
    return (float*)p;
}

extern "C" void kernel_launch(void* const* d_in, const int* in_sizes, int n_in,
                              void* d_out, int out_size) {
    const float* x      = (const float*)d_in[0];
    const float* ln_w   = (const float*)d_in[1];
    const float* ln_b   = (const float*)d_in[2];
    const float* qkv_w  = (const float*)d_in[3];
    const float* out_w  = (const float*)d_in[4];
    const float* out_b  = (const float*)d_in[5];
    const float* conv_w = (const float*)d_in[6];
    const float* omega  = (const float*)d_in[7];
    float* out = (float*)d_out;

    float* xn    = sym(g_xn);
    float* qkv   = sym(g_qkv);
    float* ql    = sym(g_ql);
    float* kl    = sym(g_kl);
    float* attn1 = sym(g_attn1);
    float* attn3 = sym(g_attn3);
    float* o1    = sym(g_o1);
    float* a2    = sym(g_a2);
    float* z     = sym(g_z);
    float* z2    = sym(g_z2);
    float* az    = sym(g_az);
    float* t1    = sym(g_t1);
    float* t2    = sym(g_t2);
    float* kv    = sym(g_kv);
    float* Y     = sym(g_y);
    float* scal  = sym(g_scal);

    const long long sA1 = (long long)N_TOK * M_LM;
    const long long sLM = (long long)M_LM * DH;
    const long long sMM = (long long)M_LM * M_LM;
    const long long sQB = (long long)N_TOK * E3;

    // 1. LayerNorm
    ln_kernel<<<BN, 256>>>(x, ln_w, ln_b, xn);

    // 2. QKV projection
    launch_t128(true, xn, qkv_w, qkv, BN, E3, DIM, DIM, DIM, E3,
                0, 0, 0, 0, 0, 0, 1, 1, 1.0f, 0.0f);

    // 3. Landmark means
    landmark_kernel<<<(BHN * M_LM * DH) / 256, 256>>>(qkv, ql, kl);

    // 4. sim1 -> softmax -> attn1 [bh,4096,256]
    launch_t128(true, qkv, kl, attn1, N_TOK, M_LM, DH, E3, DH, M_LM,
                sQB, DH, 8 * sLM, sLM, 8 * sA1, sA1, HEADS, BHN, 0.125f, 0.0f);
    softmax256_kernel<<<(BHN * N_TOK) / 8, dim3(32, 8)>>>(attn1, BHN * N_TOK);

    // 5. sim2 -> softmax -> a2 [bh,256,256]
    launch_t128(true, ql, kl, a2, M_LM, M_LM, DH, DH, DH, M_LM,
                8 * sLM, sLM, 8 * sLM, sLM, 8 * sMM, sMM, HEADS, BHN, 1.0f, 0.0f);
    softmax256_kernel<<<(BHN * M_LM) / 8, dim3(32, 8)>>>(a2, BHN * M_LM);

    // 6. sim3 -> softmax -> attn3 [bh,256,4096]
    launch_t128(true, ql, qkv + DIM, attn3, M_LM, N_TOK, DH, DH, E3, N_TOK,
                8 * sLM, sLM, sQB, DH, 8 * sA1, sA1, HEADS, BHN, 1.0f, 0.0f);
    softmax4096_kernel<<<BHN * M_LM, 256>>>(attn3);

    // 7. pinv (6 Newton-Schulz iterations)
    reset_kernel<<<1, 32>>>(scal);
    pinv_reduce_kernel<<<BHN, 256>>>(a2, scal);
    zinit_kernel<<<(BHN * (int)sMM) / 256, 256>>>(a2, z, scal);

    float* zc = z;
    float* zn = z2;
    const int eg = (BHN * (int)sMM) / 256;
    for (int it = 0; it < 6; it++) {
        launch_t128(false, a2, zc, az, M_LM, M_LM, M_LM, M_LM, M_LM, M_LM,
                    sMM, 0, sMM, 0, sMM, 0, 1, BHN, 1.0f, 0.0f);
        idminus_kernel<<<eg, 256>>>(az, t1, 7.0f);
        // t2 = 15I - az@t1
        launch_t128(false, az, t1, t2, M_LM, M_LM, M_LM, M_LM, M_LM, M_LM,
                    sMM, 0, sMM, 0, sMM, 0, 1, BHN, -1.0f, 15.0f);
        // t1 = 13I - az@t2
        launch_t128(false, az, t2, t1, M_LM, M_LM, M_LM, M_LM, M_LM, M_LM,
                    sMM, 0, sMM, 0, sMM, 0, 1, BHN, -1.0f, 13.0f);
        // zn = 0.25 * zc@t1
        launch_t128(false, zc, t1, zn, M_LM, M_LM, M_LM, M_LM, M_LM, M_LM,
                    sMM, 0, sMM, 0, sMM, 0, 1, BHN, 0.25f, 0.0f);
        float* tmp = zc; zc = zn; zn = tmp;
    }

    // 8. kv = attn3 @ v  (N=64)
    launch_t64(false, attn3, qkv + 2 * DIM, kv, M_LM, DH, N_TOK, N_TOK, E3, DH,
               8 * sA1, sA1, sQB, DH, 8 * sLM, sLM, HEADS, BHN, 1.0f, 0.0f);

    // 9. o1 = attn1 @ attn2_inv
    launch_t128(false, attn1, zc, o1, N_TOK, M_LM, M_LM, M_LM, M_LM, M_LM,
                8 * sA1, sA1, 8 * sMM, sMM, 8 * sA1, sA1, HEADS, BHN, 1.0f, 0.0f);

    // 10. Y = o1 @ kv  (N=64, written in [b,n,h*dh] layout)
    launch_t64(false, o1, kv, Y, N_TOK, DH, M_LM, M_LM, DH, DIM,
               8 * sA1, sA1, 8 * sLM, sLM, (long long)N_TOK * DIM, DH,
               HEADS, BHN, 1.0f, 0.0f);

    // 11. conv residual
    conv_add_kernel<<<dim3(N_TOK / 4, BHN), dim3(64, 4)>>>(qkv, conv_w, Y);

    // 12. out projection
    launch_t128(true, Y, out_w, out, BN, DIM, DIM, DIM, DIM, DIM,
                0, 0, 0, 0, 0, 0, 1, 1, 1.0f, 0.0f);

    // 13. final residual
    final_ep_kernel<<<(BN * DIM) / 256, 256>>>(x, out_b, omega, out);
}

// round 8
// speedup vs baseline: 3.7928x; 1.6684x over previous
#include <cuda_runtime.h>
#include <cuda_bf16.h>
#include <stdint.h>
#include <math.h>
#include <float.h>

#define B_SZ     8
#define N_TOK    4096
#define DIM      512
#define HEADS    8
#define DH       64
#define M_LM     256
#define L_PER    16
#define E3       1536
#define BN       (B_SZ * N_TOK)         // 32768
#define BHN      (B_SZ * HEADS)         // 64
#define KER      33

typedef __nv_bfloat16 bf16;

// ---------------------------------------------------------------------------
// Device scratch (bf16 for everything GEMM-facing)
// ---------------------------------------------------------------------------
__device__ __align__(256) bf16 g_xn   [BN * DIM];
__device__ __align__(256) bf16 g_qkv  [BN * E3];
__device__ __align__(256) bf16 g_ql   [BHN * M_LM * DH];
__device__ __align__(256) bf16 g_kl   [BHN * M_LM * DH];
__device__ __align__(256) bf16 g_attn1[BHN * N_TOK * M_LM];
__device__ __align__(256) bf16 g_attn3[BHN * M_LM * N_TOK];
__device__ __align__(256) bf16 g_o1   [BHN * N_TOK * M_LM];
__device__ __align__(256) bf16 g_a2   [BHN * M_LM * M_LM];
__device__ __align__(256) bf16 g_z    [BHN * M_LM * M_LM];
__device__ __align__(256) bf16 g_z2   [BHN * M_LM * M_LM];
__device__ __align__(256) bf16 g_az   [BHN * M_LM * M_LM];
__device__ __align__(256) bf16 g_t1   [BHN * M_LM * M_LM];
__device__ __align__(256) bf16 g_t2   [BHN * M_LM * M_LM];
__device__ __align__(256) bf16 g_kv   [BHN * M_LM * DH];
__device__ __align__(256) bf16 g_y    [BN * DIM];
__device__ __align__(256) bf16 g_qkvw [E3 * DIM];
__device__ __align__(256) bf16 g_outw [DIM * DIM];
__device__ __align__(256) float g_scal[2];

// ---------------------------------------------------------------------------
// Helpers
// ---------------------------------------------------------------------------
__device__ __forceinline__ uint32_t packbf(float lo, float hi) {
    uint32_t r;
    asm("cvt.rn.bf16x2.f32 %0, %1, %2;" : "=r"(r) : "f"(hi), "f"(lo));
    return r;
}
__device__ __forceinline__ uint32_t smem_u32(const void* p) {
    return (uint32_t)__cvta_generic_to_shared(p);
}
__device__ __forceinline__ void cpasync16(uint32_t dst, const void* src) {
    asm volatile("cp.async.cg.shared.global [%0], [%1], 16;" :: "r"(dst), "l"(src));
}
__device__ __forceinline__ void ldmx4(uint32_t& r0, uint32_t& r1, uint32_t& r2,
                                      uint32_t& r3, uint32_t addr) {
    asm volatile("ldmatrix.sync.aligned.m8n8.x4.shared.b16 {%0,%1,%2,%3}, [%4];"
                 : "=r"(r0), "=r"(r1), "=r"(r2), "=r"(r3) : "r"(addr));
}
__device__ __forceinline__ void ldmx4t(uint32_t& r0, uint32_t& r1, uint32_t& r2,
                                       uint32_t& r3, uint32_t addr) {
    asm volatile("ldmatrix.sync.aligned.m8n8.x4.trans.shared.b16 {%0,%1,%2,%3}, [%4];"
                 : "=r"(r0), "=r"(r1), "=r"(r2), "=r"(r3) : "r"(addr));
}
__device__ __forceinline__ void mma16816(float* c, const uint32_t* a, const uint32_t* b) {
    asm volatile("mma.sync.aligned.m16n8k16.row.col.f32.bf16.bf16.f32 "
                 "{%0,%1,%2,%3}, {%4,%5,%6,%7}, {%8,%9}, {%0,%1,%2,%3};"
                 : "+f"(c[0]), "+f"(c[1]), "+f"(c[2]), "+f"(c[3])
                 : "r"(a[0]), "r"(a[1]), "r"(a[2]), "r"(a[3]), "r"(b[0]), "r"(b[1]));
}

__device__ __forceinline__ float bredSum(float v, float* sm) {
    #pragma unroll
    for (int o = 16; o; o >>= 1) v += __shfl_xor_sync(0xffffffffu, v, o);
    int w = threadIdx.x >> 5, l = threadIdx.x & 31;
    if (l == 0) sm[w] = v;
    __syncthreads();
    if (w == 0) {
        v = (l < 8) ? sm[l] : 0.0f;
        #pragma unroll
        for (int o = 4; o; o >>= 1) v += __shfl_xor_sync(0xffffffffu, v, o);
        if (l == 0) sm[0] = v;
    }
    __syncthreads();
    v = sm[0];
    __syncthreads();
    return v;
}
__device__ __forceinline__ float bredMax(float v, float* sm) {
    #pragma unroll
    for (int o = 16; o; o >>= 1) v = fmaxf(v, __shfl_xor_sync(0xffffffffu, v, o));
    int w = threadIdx.x >> 5, l = threadIdx.x & 31;
    if (l == 0) sm[w] = v;
    __syncthreads();
    if (w == 0) {
        v = (l < 8) ? sm[l] : -FLT_MAX;
        #pragma unroll
        for (int o = 4; o; o >>= 1) v = fmaxf(v, __shfl_xor_sync(0xffffffffu, v, o));
        if (l == 0) sm[0] = v;
    }
    __syncthreads();
    v = sm[0];
    __syncthreads();
    return v;
}

// ---------------------------------------------------------------------------
// BF16 GEMM: tile 128 x (4*WN) x 16, cp.async + ldmatrix, double buffered.
// A [M,K] bf16 row-major; B: TRANSB ? [N,K] : [K,N] bf16.
// C = diag*I + alpha * A.op(B); output bf16 (or fp32 if OUTF32).
// ---------------------------------------------------------------------------
template <bool TRANSB, int WN, bool OUTF32>
__global__ void __launch_bounds__(256)
bgemm_kernel(const bf16* __restrict__ Amat, const bf16* __restrict__ Bmat,
             void* __restrict__ Cvoid, int K, int lda, int ldb, int ldc,
             long long sAo, long long sAi, long long sBo, long long sBi,
             long long sCo, long long sCi, int Hdiv, float alpha, float diag) {
    constexpr int BNT  = WN * 4;          // 128 or 64
    constexpr int NT   = WN / 8;          // 4 or 2
    constexpr int BUFA = 128 * 32;        // bytes per A tile (128 rows x 32B)
    constexpr int BUFB = BNT * 32;        // same byte count for either B layout

    __shared__ __align__(16) uint8_t smA[2 * BUFA];
    __shared__ __align__(16) uint8_t smB[2 * BUFB];

    int zb = blockIdx.z;
    int zo = zb / Hdiv, zi = zb - zo * Hdiv;
    Amat += zo * sAo + zi * sAi;
    Bmat += zo * sBo + zi * sBi;

    const int m0 = blockIdx.y * 128, n0 = blockIdx.x * BNT;
    const int tid = threadIdx.x, lane = tid & 31, warp = tid >> 5;
    const int wm = warp & 1, wn = warp >> 1;

    // ---- A writer (256 threads: 128 rows x 2 halves of 16B) ----
    const int awr = tid >> 1, awh = tid & 1;
    const uint32_t awAddr = smem_u32(smA) + awr * 32 + ((awh ^ ((awr >> 2) & 1)) << 4);
    const bf16* agp = Amat + (long long)(m0 + awr) * lda + awh * 8;

    // ---- B writer ----
    uint32_t bwAddr = 0;
    const bf16* bgp = nullptr;
    bool bact;
    long long bAdv;
    if (TRANSB) {
        bact = (BNT == 128) || (tid < 128);
        int bwr = (tid >> 1) & (BNT - 1);
        int bwh = tid & 1;
        bwAddr = smem_u32(smB) + bwr * 32 + ((bwh ^ ((bwr >> 2) & 1)) << 4);
        bgp = Bmat + (long long)(n0 + bwr) * ldb + bwh * 8;
        bAdv = 16;
    } else {
        constexpr int CH = BNT / 8;       // 16B chunks per k-row
        bact = tid < 16 * CH;
        int bk = (tid / CH) & 15, bc = tid % CH;
        bwAddr = smem_u32(smB) + bk * (BNT * 2) + (((bc ^ (bk & 7)) & (CH - 1)) << 4)
                 + ((bc & ~(CH - 1)) << 4);
        bgp = Bmat + (long long)bk * ldb + n0 + bc * 8;
        bAdv = (long long)16 * ldb;
    }

    // ---- fragment lane addressing ----
    const int rl = (lane & 7) + ((lane >> 3) & 1) * 8;
    const int lh = (lane >> 4) & 1;
    const int swz = lh ^ ((rl >> 2) & 1);
    const uint32_t aF = smem_u32(smA) + (wm * 64 + rl) * 32 + swz * 16;
    uint32_t bF[NT / 2];
    if (TRANSB) {
        #pragma unroll
        for (int p = 0; p < NT / 2; p++)
            bF[p] = smem_u32(smB) + (wn * WN + p * 16 + rl) * 32 + swz * 16;
    } else {
        const int kf = (lane & 7) + ((lane >> 4) & 1) * 8;
        const int cOff = (lane >> 3) & 1;
        #pragma unroll
        for (int p = 0; p < NT / 2; p++) {
            int ch = wn * NT + p * 2 + cOff;
            bF[p] = smem_u32(smB) + kf * (BNT * 2) + ((ch ^ (kf & 7)) << 4);
        }
    }

    float acc[4][NT][4] = {};

    const int ktiles = K >> 4;
    // prologue: tile 0 into buf 0
    cpasync16(awAddr, agp);
    if (bact) cpasync16(bwAddr, bgp);
    asm volatile("cp.async.commit_group;");
    agp += 16;
    bgp += bAdv;

    int buf = 0;
    for (int kt = 0; kt < ktiles; kt++) {
        bool more = (kt + 1) < ktiles;
        if (more) {
            int nb = buf ^ 1;
            cpasync16(awAddr + nb * BUFA, agp);
            if (bact) cpasync16(bwAddr + nb * BUFB, bgp);
            asm volatile("cp.async.commit_group;");
            agp += 16;
            bgp += bAdv;
        }
        if (more) asm volatile("cp.async.wait_group 1;");
        else      asm volatile("cp.async.wait_group 0;");
        __syncthreads();

        uint32_t a[4][4];
        #pragma unroll
        for (int mt = 0; mt < 4; mt++)
            ldmx4(a[mt][0], a[mt][1], a[mt][2], a[mt][3], aF + buf * BUFA + mt * 512);
        uint32_t bfr[NT][2];
        #pragma unroll
        for (int p = 0; p < NT / 2; p++) {
            uint32_t r0, r1, r2, r3;
            if (TRANSB) ldmx4 (r0, r1, r2, r3, bF[p] + buf * BUFB);
            else        ldmx4t(r0, r1, r2, r3, bF[p] + buf * BUFB);
            bfr[2 * p][0] = r0; bfr[2 * p + 1][0] = r1;
            bfr[2 * p][1] = r2; bfr[2 * p + 1][1] = r3;
        }
        #pragma unroll
        for (int nt = 0; nt < NT; nt++)
            #pragma unroll
            for (int mt = 0; mt < 4; mt++)
                mma16816(&acc[mt][nt][0], &a[mt][0], &bfr[nt][0]);
        __syncthreads();
        buf ^= 1;
    }

    // ---- epilogue ----
    const int g = lane >> 2, t4 = lane & 3;
    if (OUTF32) {
        float* Cm = (float*)Cvoid + zo * sCo + zi * sCi;
        #pragma unroll
        for (int mt = 0; mt < 4; mt++) {
            int r0 = m0 + wm * 64 + mt * 16 + g;
            #pragma unroll
            for (int nt = 0; nt < NT; nt++) {
                int c0 = n0 + wn * WN + nt * 8 + t4 * 2;
                float2 v0, v1;
                v0.x = alpha * acc[mt][nt][0] + ((r0 == c0)     ? diag : 0.0f);
                v0.y = alpha * acc[mt][nt][1] + ((r0 == c0 + 1) ? diag : 0.0f);
                v1.x = alpha * acc[mt][nt][2] + ((r0 + 8 == c0)     ? diag : 0.0f);
                v1.y = alpha * acc[mt][nt][3] + ((r0 + 8 == c0 + 1) ? diag : 0.0f);
                *(float2*)(Cm + (long long)r0 * ldc + c0) = v0;
                *(float2*)(Cm + (long long)(r0 + 8) * ldc + c0) = v1;
            }
        }
    } else {
        bf16* Cm = (bf16*)Cvoid + zo * sCo + zi * sCi;
        #pragma unroll
        for (int mt = 0; mt < 4; mt++) {
            int r0 = m0 + wm * 64 + mt * 16 + g;
            #pragma unroll
            for (int nt = 0; nt < NT; nt++) {
                int c0 = n0 + wn * WN + nt * 8 + t4 * 2;
                float e0 = alpha * acc[mt][nt][0] + ((r0 == c0)     ? diag : 0.0f);
                float e1 = alpha * acc[mt][nt][1] + ((r0 == c0 + 1) ? diag : 0.0f);
                float e2 = alpha * acc[mt][nt][2] + ((r0 + 8 == c0)     ? diag : 0.0f);
                float e3 = alpha * acc[mt][nt][3] + ((r0 + 8 == c0 + 1) ? diag : 0.0f);
                *(uint32_t*)(Cm + (long long)r0 * ldc + c0) = packbf(e0, e1);
                *(uint32_t*)(Cm + (long long)(r0 + 8) * ldc + c0) = packbf(e2, e3);
            }
        }
    }
}

static inline void launch_b128(bool transB, const bf16* A, const bf16* Bm, bf16* C,
                               int M, int N, int K, int lda, int ldb, int ldc,
                               long long sAo, long long sAi, long long sBo, long long sBi,
                               long long sCo, long long sCi, int Hdiv, int batch,
                               float alpha, float diag) {
    dim3 grid(N / 128, M / 128, batch), block(256);
    if (transB)
        bgemm_kernel<true, 32, false><<<grid, block>>>(A, Bm, C, K, lda, ldb, ldc,
            sAo, sAi, sBo, sBi, sCo, sCi, Hdiv, alpha, diag);
    else
        bgemm_kernel<false, 32, false><<<grid, block>>>(A, Bm, C, K, lda, ldb, ldc,
            sAo, sAi, sBo, sBi, sCo, sCi, Hdiv, alpha, diag);
}

static inline void launch_b64(bool transB, const bf16* A, const bf16* Bm, bf16* C,
                              int M, int N, int K, int lda, int ldb, int ldc,
                              long long sAo, long long sAi, long long sBo, long long sBi,
                              long long sCo, long long sCi, int Hdiv, int batch,
                              float alpha, float diag) {
    dim3 grid(N / 64, M / 128, batch), block(256);
    if (transB)
        bgemm_kernel<true, 16, false><<<grid, block>>>(A, Bm, C, K, lda, ldb, ldc,
            sAo, sAi, sBo, sBi, sCo, sCi, Hdiv, alpha, diag);
    else
        bgemm_kernel<false, 16, false><<<grid, block>>>(A, Bm, C, K, lda, ldb, ldc,
            sAo, sAi, sBo, sBi, sCo, sCi, Hdiv, alpha, diag);
}

// ---------------------------------------------------------------------------
// fp32 -> bf16 weight conversion
// ---------------------------------------------------------------------------
__global__ void f2b_kernel(const float4* __restrict__ in, uint2* __restrict__ out, int n4) {
    int i = blockIdx.x * 256 + threadIdx.x;
    if (i < n4) {
        float4 v = in[i];
        out[i] = make_uint2(packbf(v.x, v.y), packbf(v.z, v.w));
    }
}

// ---------------------------------------------------------------------------
// LayerNorm (fp32 in -> bf16 out)
// ---------------------------------------------------------------------------
__global__ void ln_kernel(const float* __restrict__ x, const float* __restrict__ w,
                          const float* __restrict__ bias, bf16* __restrict__ o) {
    __shared__ float sm[32];
    long long row = blockIdx.x;
    const float2* xr = (const float2*)(x + row * DIM);
    int t = threadIdx.x;
    float2 v = xr[t];
    float mu = bredSum(v.x + v.y, sm) * (1.0f / DIM);
    float d0 = v.x - mu, d1 = v.y - mu;
    float var = bredSum(d0 * d0 + d1 * d1, sm) * (1.0f / DIM);
    float rs = rsqrtf(var + 1e-5f);
    float2 wv = ((const float2*)w)[t];
    float2 bv = ((const float2*)bias)[t];
    ((uint32_t*)(o + row * DIM))[t] = packbf(d0 * rs * wv.x + bv.x, d1 * rs * wv.y + bv.y);
}

// ---------------------------------------------------------------------------
// Landmark means (bf16)
// ---------------------------------------------------------------------------
__global__ void landmark_kernel(const bf16* __restrict__ qkv,
                                bf16* __restrict__ ql, bf16* __restrict__ kl) {
    int idx = blockIdx.x * 256 + threadIdx.x;
    int d  = idx & 63;
    int mi = (idx >> 6) & 255;
    int bh = idx >> 14;
    int bb = bh >> 3, h = bh & 7;
    const bf16* base = qkv + ((long long)(bb * N_TOK + mi * L_PER)) * E3 + h * DH + d;
    float sq = 0.f, sk = 0.f;
    #pragma unroll
    for (int j = 0; j < L_PER; j++) {
        sq += __bfloat162float(base[(long long)j * E3]);
        sk += __bfloat162float(base[(long long)j * E3 + DIM]);
    }
    ql[idx] = __float2bfloat16(sq * (0.125f / 16.0f));
    kl[idx] = __float2bfloat16(sk * (1.0f / 16.0f));
}

// ---------------------------------------------------------------------------
// Softmax over rows of 256 (warp per row)
// ---------------------------------------------------------------------------
__global__ void softmax256_kernel(bf16* __restrict__ data, int rows) {
    int row = blockIdx.x * 8 + threadIdx.y;
    if (row >= rows) return;
    uint32_t* p = (uint32_t*)(data + (long long)row * 256);
    int lane = threadIdx.x;
    float2 v[4];
    #pragma unroll
    for (int j = 0; j < 4; j++) {
        uint32_t wv = p[lane + j * 32];
        v[j] = __bfloat1622float2(*(__nv_bfloat162*)&wv);
    }
    float mx = -FLT_MAX;
    #pragma unroll
    for (int j = 0; j < 4; j++) mx = fmaxf(mx, fmaxf(v[j].x, v[j].y));
    #pragma unroll
    for (int o = 16; o; o >>= 1) mx = fmaxf(mx, __shfl_xor_sync(0xffffffffu, mx, o));
    float s = 0.f;
    #pragma unroll
    for (int j = 0; j < 4; j++) {
        v[j].x = expf(v[j].x - mx); v[j].y = expf(v[j].y - mx);
        s += v[j].x + v[j].y;
    }
    #pragma unroll
    for (int o = 16; o; o >>= 1) s += __shfl_xor_sync(0xffffffffu, s, o);
    float inv = 1.0f / s;
    #pragma unroll
    for (int j = 0; j < 4; j++)
        p[lane + j * 32] = packbf(v[j].x * inv, v[j].y * inv);
}

// ---------------------------------------------------------------------------
// Softmax over rows of 4096 (block per row)
// ---------------------------------------------------------------------------
__global__ void softmax4096_kernel(bf16* __restrict__ data) {
    __shared__ float sm[32];
    uint32_t* p = (uint32_t*)(data + (long long)blockIdx.x * N_TOK);
    int t = threadIdx.x;
    float2 v[8];
    #pragma unroll
    for (int j = 0; j < 8; j++) {
        uint32_t wv = p[t + j * 256];
        v[j] = __bfloat1622float2(*(__nv_bfloat162*)&wv);
    }
    float mx = -FLT_MAX;
    #pragma unroll
    for (int j = 0; j < 8; j++) mx = fmaxf(mx, fmaxf(v[j].x, v[j].y));
    mx = bredMax(mx, sm);
    float s = 0.f;
    #pragma unroll
    for (int j = 0; j < 8; j++) {
        v[j].x = expf(v[j].x - mx); v[j].y = expf(v[j].y - mx);
        s += v[j].x + v[j].y;
    }
    s = bredSum(s, sm);
    float inv = 1.0f / s;
    #pragma unroll
    for (int j = 0; j < 8; j++)
        p[t + j * 256] = packbf(v[j].x * inv, v[j].y * inv);
}

// ---------------------------------------------------------------------------
// pinv helpers
// ---------------------------------------------------------------------------
__global__ void reset_kernel(float* scal) {
    if (threadIdx.x < 2) scal[threadIdx.x] = 0.0f;
}

__global__ void pinv_reduce_kernel(const bf16* __restrict__ a2, float* __restrict__ scal) {
    int bh = blockIdx.x, j = threadIdx.x;
    const bf16* a = a2 + (long long)bh * (M_LM * M_LM);
    float cs = 0.f, rs = 0.f;
    for (int i = 0; i < M_LM; i++) {
        cs += fabsf(__bfloat162float(a[i * M_LM + j]));
        rs += fabsf(__bfloat162float(a[j * M_LM + i]));
    }
    atomicMax((int*)&scal[0], __float_as_int(rs));
    atomicMax((int*)&scal[1], __float_as_int(cs));
}

__global__ void zinit_kernel(const bf16* __restrict__ a2, bf16* __restrict__ z,
                             const float* __restrict__ scal) {
    float inv = 1.0f / (scal[0] * scal[1]);
    int idx = blockIdx.x * 256 + threadIdx.x;
    int bh = idx >> 16, r = (idx >> 8) & 255, c = idx & 255;
    z[idx] = __float2bfloat16(
        __bfloat162float(a2[((long long)bh << 16) + (c << 8) + r]) * inv);
}

__global__ void idminus_kernel(const bf16* __restrict__ in, bf16* __restrict__ out,
                               float alpha) {
    int idx = blockIdx.x * 256 + threadIdx.x;
    int r = (idx >> 8) & 255, c = idx & 255;
    out[idx] = __float2bfloat16(((r == c) ? alpha : 0.0f) - __bfloat162float(in[idx]));
}

// ---------------------------------------------------------------------------
// Depthwise residual conv (reads bf16 v, adds into bf16 Y)
// ---------------------------------------------------------------------------
__global__ void conv_add_kernel(const bf16* __restrict__ qkv, const float* __restrict__ cw,
                                bf16* __restrict__ Y) {
    __shared__ float w[KER];
    int bh = blockIdx.y;
    int bb = bh >> 3, h = bh & 7;
    int tid = threadIdx.y * 64 + threadIdx.x;
    if (tid < KER) w[tid] = cw[h * KER + tid];
    __syncthreads();
    int j = threadIdx.x;
    int i = blockIdx.x * 4 + threadIdx.y;
    const bf16* vb = qkv + (long long)bb * N_TOK * E3 + 2 * DIM + h * DH + j;
    float acc = 0.f;
    #pragma unroll
    for (int t = 0; t < KER; t++) {
        int r = i + t - KER / 2;
        if (r >= 0 && r < N_TOK) acc += w[t] * __bfloat162float(vb[(long long)r * E3]);
    }
    long long o = ((long long)(bb * N_TOK + i)) * DIM + h * DH + j;
    Y[o] = __float2bfloat16(__bfloat162float(Y[o]) + acc);
}

// ---------------------------------------------------------------------------
// Final epilogue (fp32)
// ---------------------------------------------------------------------------
__global__ void final_ep_kernel(const float* __restrict__ x, const float* __restrict__ ob,
                                const float* __restrict__ omega, float* __restrict__ out) {
    long long idx = (long long)blockIdx.x * 256 + threadIdx.x;
    out[idx] = x[idx] * omega[0] + out[idx] + ob[idx & (DIM - 1)];
}

// ---------------------------------------------------------------------------
// Launcher
// ---------------------------------------------------------------------------
template <typename T>
static T* symp(T& s) {
    void* p = nullptr;
    cudaGetSymbolAddress(&p, s);
    return (T*)p;
}
template <typename T, size_t N>
static T* symp(T (&s)[N]) {
    void* p = nullptr;
    cudaGetSymbolAddress(&p, s);
    return (T*)p;
}

extern "C" void kernel_launch(void* const* d_in, const int* in_sizes, int n_in,
                              void* d_out, int out_size) {
    const float* x      = (const float*)d_in[0];
    const float* ln_w   = (const float*)d_in[1];
    const float* ln_b   = (const float*)d_in[2];
    const float* qkv_w  = (const float*)d_in[3];
    const float* out_w  = (const float*)d_in[4];
    const float* out_b  = (const float*)d_in[5];
    const float* conv_w = (const float*)d_in[6];
    const float* omega  = (const float*)d_in[7];
    float* out = (float*)d_out;

    bf16* xn    = symp(g_xn);
    bf16* qkv   = symp(g_qkv);
    bf16* ql    = symp(g_ql);
    bf16* kl    = symp(g_kl);
    bf16* attn1 = symp(g_attn1);
    bf16* attn3 = symp(g_attn3);
    bf16* o1    = symp(g_o1);
    bf16* a2    = symp(g_a2);
    bf16* z     = symp(g_z);
    bf16* z2    = symp(g_z2);
    bf16* az    = symp(g_az);
    bf16* t1    = symp(g_t1);
    bf16* t2    = symp(g_t2);
    bf16* kv    = symp(g_kv);
    bf16* Y     = symp(g_y);
    bf16* qkvwb = symp(g_qkvw);
    bf16* outwb = symp(g_outw);
    float* scal = symp(g_scal);

    const long long sA1 = (long long)N_TOK * M_LM;
    const long long sLM = (long long)M_LM * DH;
    const long long sMM = (long long)M_LM * M_LM;
    const long long sQB = (long long)N_TOK * E3;

    // 0. Weight conversion fp32 -> bf16
    f2b_kernel<<<(E3 * DIM / 4 + 255) / 256, 256>>>((const float4*)qkv_w, (uint2*)qkvwb,
                                                    E3 * DIM / 4);
    f2b_kernel<<<(DIM * DIM / 4 + 255) / 256, 256>>>((const float4*)out_w, (uint2*)outwb,
                                                     DIM * DIM / 4);

    // 1. LayerNorm
    ln_kernel<<<BN, 256>>>(x, ln_w, ln_b, xn);

    // 2. QKV projection
    launch_b128(true, xn, qkvwb, qkv, BN, E3, DIM, DIM, DIM, E3,
                0, 0, 0, 0, 0, 0, 1, 1, 1.0f, 0.0f);

    // 3. Landmark means
    landmark_kernel<<<(BHN * M_LM * DH) / 256, 256>>>(qkv, ql, kl);

    // 4. sim1 -> softmax -> attn1
    launch_b128(true, qkv, kl, attn1, N_TOK, M_LM, DH, E3, DH, M_LM,
                sQB, DH, 8 * sLM, sLM, 8 * sA1, sA1, HEADS, BHN, 0.125f, 0.0f);
    softmax256_kernel<<<(BHN * N_TOK) / 8, dim3(32, 8)>>>(attn1, BHN * N_TOK);

    // 5. sim2 -> softmax -> a2
    launch_b128(true, ql, kl, a2, M_LM, M_LM, DH, DH, DH, M_LM,
                8 * sLM, sLM, 8 * sLM, sLM, 8 * sMM, sMM, HEADS, BHN, 1.0f, 0.0f);
    softmax256_kernel<<<(BHN * M_LM) / 8, dim3(32, 8)>>>(a2, BHN * M_LM);

    // 6. sim3 -> softmax -> attn3
    launch_b128(true, ql, qkv + DIM, attn3, M_LM, N_TOK, DH, DH, E3, N_TOK,
                8 * sLM, sLM, sQB, DH, 8 * sA1, sA1, HEADS, BHN, 1.0f, 0.0f);
    softmax4096_kernel<<<BHN * M_LM, 256>>>(attn3);

    // 7. pinv (6 Newton-Schulz iterations)
    reset_kernel<<<1, 32>>>(scal);
    pinv_reduce_kernel<<<BHN, 256>>>(a2, scal);
    zinit_kernel<<<(BHN * (int)sMM) / 256, 256>>>(a2, z, scal);

    bf16* zc = z;
    bf16* zn = z2;
    const int eg = (BHN * (int)sMM) / 256;
    for (int it = 0; it < 6; it++) {
        launch_b128(false, a2, zc, az, M_LM, M_LM, M_LM, M_LM, M_LM, M_LM,
                    sMM, 0, sMM, 0, sMM, 0, 1, BHN, 1.0f, 0.0f);
        idminus_kernel<<<eg, 256>>>(az, t1, 7.0f);
        launch_b128(false, az, t1, t2, M_LM, M_LM, M_LM, M_LM, M_LM, M_LM,
                    sMM, 0, sMM, 0, sMM, 0, 1, BHN, -1.0f, 15.0f);
        launch_b128(false, az, t2, t1, M_LM, M_LM, M_LM, M_LM, M_LM, M_LM,
                    sMM, 0, sMM, 0, sMM, 0, 1, BHN, -1.0f, 13.0f);
        launch_b128(false, zc, t1, zn, M_LM, M_LM, M_LM, M_LM, M_LM, M_LM,
                    sMM, 0, sMM, 0, sMM, 0, 1, BHN, 0.25f, 0.0f);
        bf16* tmp = zc; zc = zn; zn = tmp;
    }

    // 8. kv = attn3 @ v
    launch_b64(false, attn3, qkv + 2 * DIM, kv, M_LM, DH, N_TOK, N_TOK, E3, DH,
               8 * sA1, sA1, sQB, DH, 8 * sLM, sLM, HEADS, BHN, 1.0f, 0.0f);

    // 9. o1 = attn1 @ attn2_inv
    launch_b128(false, attn1, zc, o1, N_TOK, M_LM, M_LM, M_LM, M_LM, M_LM,
                8 * sA1, sA1, 8 * sMM, sMM, 8 * sA1, sA1, HEADS, BHN, 1.0f, 0.0f);

    // 10. Y = o1 @ kv (written in [b,n,h*dh] layout)
    launch_b64(false, o1, kv, Y, N_TOK, DH, M_LM, M_LM, DH, DIM,
               8 * sA1, sA1, 8 * sLM, sLM, (long long)N_TOK * DIM, DH,
               HEADS, BHN, 1.0f, 0.0f);

    // 11. conv residual
    conv_add_kernel<<<dim3(N_TOK / 4, BHN), dim3(64, 4)>>>(qkv, conv_w, Y);

    // 12. out projection (fp32 output)
    {
        dim3 grid(DIM / 128, BN / 128, 1), block(256);
        bgemm_kernel<true, 32, true><<<grid, block>>>(Y, outwb, (void*)out,
            DIM, DIM, DIM, DIM, 0, 0, 0, 0, 0, 0, 1, 1.0f, 0.0f);
    }

    // 13. final residual
    final_ep_kernel<<<(BN * DIM) / 256, 256>>>(x, out_b, omega, out);
}

// round 10
// speedup vs baseline: 4.9007x; 1.2921x over previous
#include <cuda_runtime.h>
#include <cuda_bf16.h>
#include <stdint.h>
#include <math.h>
#include <float.h>

#define B_SZ     8
#define N_TOK    4096
#define DIM      512
#define HEADS    8
#define DH       64
#define M_LM     256
#define L_PER    16
#define E3       1536
#define BN       (B_SZ * N_TOK)         // 32768
#define BHN      (B_SZ * HEADS)         // 64
#define KER      33

typedef __nv_bfloat16 bf16;

// ---------------------------------------------------------------------------
// Device scratch (bf16 for everything GEMM-facing)
// ---------------------------------------------------------------------------
__device__ __align__(256) bf16 g_xn   [BN * DIM];
__device__ __align__(256) bf16 g_qkv  [BN * E3];
__device__ __align__(256) bf16 g_ql   [BHN * M_LM * DH];
__device__ __align__(256) bf16 g_kl   [BHN * M_LM * DH];
__device__ __align__(256) bf16 g_attn1[BHN * N_TOK * M_LM];
__device__ __align__(256) bf16 g_attn3[BHN * M_LM * N_TOK];
__device__ __align__(256) bf16 g_o1   [BHN * N_TOK * M_LM];
__device__ __align__(256) bf16 g_a2   [BHN * M_LM * M_LM];
__device__ __align__(256) bf16 g_z    [BHN * M_LM * M_LM];
__device__ __align__(256) bf16 g_z2   [BHN * M_LM * M_LM];
__device__ __align__(256) bf16 g_az   [BHN * M_LM * M_LM];
__device__ __align__(256) bf16 g_t1   [BHN * M_LM * M_LM];
__device__ __align__(256) bf16 g_t2   [BHN * M_LM * M_LM];
__device__ __align__(256) bf16 g_kv   [BHN * M_LM * DH];
__device__ __align__(256) bf16 g_y    [BN * DIM];
__device__ __align__(256) bf16 g_qkvw [E3 * DIM];
__device__ __align__(256) bf16 g_outw [DIM * DIM];
__device__ __align__(256) float g_scal[2];

// ---------------------------------------------------------------------------
// Helpers
// ---------------------------------------------------------------------------
__device__ __forceinline__ uint32_t packbf(float lo, float hi) {
    uint32_t r;
    asm("cvt.rn.bf16x2.f32 %0, %1, %2;" : "=r"(r) : "f"(hi), "f"(lo));
    return r;
}
__device__ __forceinline__ uint32_t smem_u32(const void* p) {
    return (uint32_t)__cvta_generic_to_shared(p);
}
__device__ __forceinline__ void cpasync16(uint32_t dst, const void* src) {
    asm volatile("cp.async.cg.shared.global [%0], [%1], 16;" :: "r"(dst), "l"(src));
}
__device__ __forceinline__ void ldmx4(uint32_t& r0, uint32_t& r1, uint32_t& r2,
                                      uint32_t& r3, uint32_t addr) {
    asm volatile("ldmatrix.sync.aligned.m8n8.x4.shared.b16 {%0,%1,%2,%3}, [%4];"
                 : "=r"(r0), "=r"(r1), "=r"(r2), "=r"(r3) : "r"(addr));
}
__device__ __forceinline__ void ldmx4t(uint32_t& r0, uint32_t& r1, uint32_t& r2,
                                       uint32_t& r3, uint32_t addr) {
    asm volatile("ldmatrix.sync.aligned.m8n8.x4.trans.shared.b16 {%0,%1,%2,%3}, [%4];"
                 : "=r"(r0), "=r"(r1), "=r"(r2), "=r"(r3) : "r"(addr));
}
__device__ __forceinline__ void mma16816(float* c, const uint32_t* a, const uint32_t* b) {
    asm volatile("mma.sync.aligned.m16n8k16.row.col.f32.bf16.bf16.f32 "
                 "{%0,%1,%2,%3}, {%4,%5,%6,%7}, {%8,%9}, {%0,%1,%2,%3};"
                 : "+f"(c[0]), "+f"(c[1]), "+f"(c[2]), "+f"(c[3])
                 : "r"(a[0]), "r"(a[1]), "r"(a[2]), "r"(a[3]), "r"(b[0]), "r"(b[1]));
}

__device__ __forceinline__ float bredSum(float v, float* sm) {
    #pragma unroll
    for (int o = 16; o; o >>= 1) v += __shfl_xor_sync(0xffffffffu, v, o);
    int w = threadIdx.x >> 5, l = threadIdx.x & 31;
    if (l == 0) sm[w] = v;
    __syncthreads();
    if (w == 0) {
        v = (l < 8) ? sm[l] : 0.0f;
        #pragma unroll
        for (int o = 4; o; o >>= 1) v += __shfl_xor_sync(0xffffffffu, v, o);
        if (l == 0) sm[0] = v;
    }
    __syncthreads();
    v = sm[0];
    __syncthreads();
    return v;
}
__device__ __forceinline__ float bredMax(float v, float* sm) {
    #pragma unroll
    for (int o = 16; o; o >>= 1) v = fmaxf(v, __shfl_xor_sync(0xffffffffu, v, o));
    int w = threadIdx.x >> 5, l = threadIdx.x & 31;
    if (l == 0) sm[w] = v;
    __syncthreads();
    if (w == 0) {
        v = (l < 8) ? sm[l] : -FLT_MAX;
        #pragma unroll
        for (int o = 4; o; o >>= 1) v = fmaxf(v, __shfl_xor_sync(0xffffffffu, v, o));
        if (l == 0) sm[0] = v;
    }
    __syncthreads();
    v = sm[0];
    __syncthreads();
    return v;
}

// ---------------------------------------------------------------------------
// BF16 GEMM: tile 128 x (4*WN) x 16, 4-stage cp.async pipeline + ldmatrix.
// A [M,K] bf16 row-major; B: TRANSB ? [N,K] : [K,N] bf16.
// C = diag*I + alpha * A.op(B); output bf16 (or fp32 if OUTF32).
// ---------------------------------------------------------------------------
template <bool TRANSB, int WN, bool OUTF32>
__global__ void __launch_bounds__(256)
bgemm_kernel(const bf16* __restrict__ Amat, const bf16* __restrict__ Bmat,
             void* __restrict__ Cvoid, int K, int lda, int ldb, int ldc,
             long long sAo, long long sAi, long long sBo, long long sBi,
             long long sCo, long long sCi, int Hdiv, float alpha, float diag) {
    constexpr int BNT  = WN * 4;          // 128 or 64
    constexpr int NT   = WN / 8;          // 4 or 2
    constexpr int BUFA = 128 * 32;        // bytes per A stage
    constexpr int BUFB = BNT * 32;        // bytes per B stage

    __shared__ __align__(16) uint8_t smA[4 * BUFA];
    __shared__ __align__(16) uint8_t smB[4 * BUFB];

    int zb = blockIdx.z;
    int zo = zb / Hdiv, zi = zb - zo * Hdiv;
    Amat += zo * sAo + zi * sAi;
    Bmat += zo * sBo + zi * sBi;

    const int m0 = blockIdx.y * 128, n0 = blockIdx.x * BNT;
    const int tid = threadIdx.x, lane = tid & 31, warp = tid >> 5;
    const int wm = warp & 1, wn = warp >> 1;

    // ---- A writer (256 threads: 128 rows x 2 halves of 16B) ----
    const int awr = tid >> 1, awh = tid & 1;
    const uint32_t awAddr = smem_u32(smA) + awr * 32 + ((awh ^ ((awr >> 2) & 1)) << 4);
    const bf16* agp = Amat + (long long)(m0 + awr) * lda + awh * 8;

    // ---- B writer ----
    uint32_t bwAddr = 0;
    const bf16* bgp = nullptr;
    bool bact;
    long long bAdv;
    if (TRANSB) {
        bact = (BNT == 128) || (tid < 128);
        int bwr = (tid >> 1) & (BNT - 1);
        int bwh = tid & 1;
        bwAddr = smem_u32(smB) + bwr * 32 + ((bwh ^ ((bwr >> 2) & 1)) << 4);
        bgp = Bmat + (long long)(n0 + bwr) * ldb + bwh * 8;
        bAdv = 16;
    } else {
        constexpr int CH = BNT / 8;       // 16B chunks per k-row
        bact = tid < 16 * CH;
        int bk = (tid / CH) & 15, bc = tid % CH;
        bwAddr = smem_u32(smB) + bk * (BNT * 2) + (((bc ^ (bk & 7)) & (CH - 1)) << 4)
                 + ((bc & ~(CH - 1)) << 4);
        bgp = Bmat + (long long)bk * ldb + n0 + bc * 8;
        bAdv = (long long)16 * ldb;
    }

    // ---- fragment lane addressing ----
    const int rl = (lane & 7) + ((lane >> 3) & 1) * 8;
    const int lh = (lane >> 4) & 1;
    const int swz = lh ^ ((rl >> 2) & 1);
    const uint32_t aF = smem_u32(smA) + (wm * 64 + rl) * 32 + swz * 16;
    uint32_t bF[NT / 2];
    if (TRANSB) {
        #pragma unroll
        for (int p = 0; p < NT / 2; p++)
            bF[p] = smem_u32(smB) + (wn * WN + p * 16 + rl) * 32 + swz * 16;
    } else {
        const int kf = (lane & 7) + ((lane >> 4) & 1) * 8;
        const int cOff = (lane >> 3) & 1;
        #pragma unroll
        for (int p = 0; p < NT / 2; p++) {
            int ch = wn * NT + p * 2 + cOff;
            bF[p] = smem_u32(smB) + kf * (BNT * 2) + ((ch ^ (kf & 7)) << 4);
        }
    }

    float acc[4][NT][4] = {};

    const int ktiles = K >> 4;

    // ---- prologue: issue stages 0..2 ----
    #pragma unroll
    for (int s = 0; s < 3; s++) {
        if (s < ktiles) {
            cpasync16(awAddr + s * BUFA, agp);
            if (bact) cpasync16(bwAddr + s * BUFB, bgp);
            agp += 16;
            bgp += bAdv;
        }
        asm volatile("cp.async.commit_group;");
    }

    for (int kt = 0; kt < ktiles; kt++) {
        asm volatile("cp.async.wait_group 2;");
        __syncthreads();
        const int slot = kt & 3;
        // issue stage kt+3 into slot (kt+3)&3 (freed at iteration kt-1)
        if (kt + 3 < ktiles) {
            int ws = (kt + 3) & 3;
            cpasync16(awAddr + ws * BUFA, agp);
            if (bact) cpasync16(bwAddr + ws * BUFB, bgp);
            agp += 16;
            bgp += bAdv;
        }
        asm volatile("cp.async.commit_group;");

        uint32_t a[4][4];
        #pragma unroll
        for (int mt = 0; mt < 4; mt++)
            ldmx4(a[mt][0], a[mt][1], a[mt][2], a[mt][3], aF + slot * BUFA + mt * 512);
        uint32_t bfr[NT][2];
        #pragma unroll
        for (int p = 0; p < NT / 2; p++) {
            uint32_t r0, r1, r2, r3;
            if (TRANSB) ldmx4 (r0, r1, r2, r3, bF[p] + slot * BUFB);
            else        ldmx4t(r0, r1, r2, r3, bF[p] + slot * BUFB);
            bfr[2 * p][0] = r0; bfr[2 * p + 1][0] = r1;
            bfr[2 * p][1] = r2; bfr[2 * p + 1][1] = r3;
        }
        #pragma unroll
        for (int nt = 0; nt < NT; nt++)
            #pragma unroll
            for (int mt = 0; mt < 4; mt++)
                mma16816(&acc[mt][nt][0], &a[mt][0], &bfr[nt][0]);
    }

    // ---- epilogue ----
    const int g = lane >> 2, t4 = lane & 3;
    if (OUTF32) {
        float* Cm = (float*)Cvoid + zo * sCo + zi * sCi;
        #pragma unroll
        for (int mt = 0; mt < 4; mt++) {
            int r0 = m0 + wm * 64 + mt * 16 + g;
            #pragma unroll
            for (int nt = 0; nt < NT; nt++) {
                int c0 = n0 + wn * WN + nt * 8 + t4 * 2;
                float2 v0, v1;
                v0.x = alpha * acc[mt][nt][0] + ((r0 == c0)     ? diag : 0.0f);
                v0.y = alpha * acc[mt][nt][1] + ((r0 == c0 + 1) ? diag : 0.0f);
                v1.x = alpha * acc[mt][nt][2] + ((r0 + 8 == c0)     ? diag : 0.0f);
                v1.y = alpha * acc[mt][nt][3] + ((r0 + 8 == c0 + 1) ? diag : 0.0f);
                *(float2*)(Cm + (long long)r0 * ldc + c0) = v0;
                *(float2*)(Cm + (long long)(r0 + 8) * ldc + c0) = v1;
            }
        }
    } else {
        bf16* Cm = (bf16*)Cvoid + zo * sCo + zi * sCi;
        #pragma unroll
        for (int mt = 0; mt < 4; mt++) {
            int r0 = m0 + wm * 64 + mt * 16 + g;
            #pragma unroll
            for (int nt = 0; nt < NT; nt++) {
                int c0 = n0 + wn * WN + nt * 8 + t4 * 2;
                float e0 = alpha * acc[mt][nt][0] + ((r0 == c0)     ? diag : 0.0f);
                float e1 = alpha * acc[mt][nt][1] + ((r0 == c0 + 1) ? diag : 0.0f);
                float e2 = alpha * acc[mt][nt][2] + ((r0 + 8 == c0)     ? diag : 0.0f);
                float e3 = alpha * acc[mt][nt][3] + ((r0 + 8 == c0 + 1) ? diag : 0.0f);
                *(uint32_t*)(Cm + (long long)r0 * ldc + c0) = packbf(e0, e1);
                *(uint32_t*)(Cm + (long long)(r0 + 8) * ldc + c0) = packbf(e2, e3);
            }
        }
    }
}

static inline void launch_b128(bool transB, const bf16* A, const bf16* Bm, bf16* C,
                               int M, int N, int K, int lda, int ldb, int ldc,
                               long long sAo, long long sAi, long long sBo, long long sBi,
                               long long sCo, long long sCi, int Hdiv, int batch,
                               float alpha, float diag) {
    dim3 grid(N / 128, M / 128, batch), block(256);
    if (transB)
        bgemm_kernel<true, 32, false><<<grid, block>>>(A, Bm, C, K, lda, ldb, ldc,
            sAo, sAi, sBo, sBi, sCo, sCi, Hdiv, alpha, diag);
    else
        bgemm_kernel<false, 32, false><<<grid, block>>>(A, Bm, C, K, lda, ldb, ldc,
            sAo, sAi, sBo, sBi, sCo, sCi, Hdiv, alpha, diag);
}

static inline void launch_b64(bool transB, const bf16* A, const bf16* Bm, bf16* C,
                              int M, int N, int K, int lda, int ldb, int ldc,
                              long long sAo, long long sAi, long long sBo, long long sBi,
                              long long sCo, long long sCi, int Hdiv, int batch,
                              float alpha, float diag) {
    dim3 grid(N / 64, M / 128, batch), block(256);
    if (transB)
        bgemm_kernel<true, 16, false><<<grid, block>>>(A, Bm, C, K, lda, ldb, ldc,
            sAo, sAi, sBo, sBi, sCo, sCi, Hdiv, alpha, diag);
    else
        bgemm_kernel<false, 16, false><<<grid, block>>>(A, Bm, C, K, lda, ldb, ldc,
            sAo, sAi, sBo, sBi, sCo, sCi, Hdiv, alpha, diag);
}

// ---------------------------------------------------------------------------
// fp32 -> bf16 weight conversion
// ---------------------------------------------------------------------------
__global__ void f2b_kernel(const float4* __restrict__ in, uint2* __restrict__ out, int n4) {
    int i = blockIdx.x * 256 + threadIdx.x;
    if (i < n4) {
        float4 v = in[i];
        out[i] = make_uint2(packbf(v.x, v.y), packbf(v.z, v.w));
    }
}

// ---------------------------------------------------------------------------
// LayerNorm (fp32 in -> bf16 out)
// ---------------------------------------------------------------------------
__global__ void ln_kernel(const float* __restrict__ x, const float* __restrict__ w,
                          const float* __restrict__ bias, bf16* __restrict__ o) {
    __shared__ float sm[32];
    long long row = blockIdx.x;
    const float2* xr = (const float2*)(x + row * DIM);
    int t = threadIdx.x;
    float2 v = xr[t];
    float mu = bredSum(v.x + v.y, sm) * (1.0f / DIM);
    float d0 = v.x - mu, d1 = v.y - mu;
    float var = bredSum(d0 * d0 + d1 * d1, sm) * (1.0f / DIM);
    float rs = rsqrtf(var + 1e-5f);
    float2 wv = ((const float2*)w)[t];
    float2 bv = ((const float2*)bias)[t];
    ((uint32_t*)(o + row * DIM))[t] = packbf(d0 * rs * wv.x + bv.x, d1 * rs * wv.y + bv.y);
}

// ---------------------------------------------------------------------------
// Landmark means (bf16)
// ---------------------------------------------------------------------------
__global__ void landmark_kernel(const bf16* __restrict__ qkv,
                                bf16* __restrict__ ql, bf16* __restrict__ kl) {
    int idx = blockIdx.x * 256 + threadIdx.x;
    int d  = idx & 63;
    int mi = (idx >> 6) & 255;
    int bh = idx >> 14;
    int bb = bh >> 3, h = bh & 7;
    const bf16* base = qkv + ((long long)(bb * N_TOK + mi * L_PER)) * E3 + h * DH + d;
    float sq = 0.f, sk = 0.f;
    #pragma unroll
    for (int j = 0; j < L_PER; j++) {
        sq += __bfloat162float(base[(long long)j * E3]);
        sk += __bfloat162float(base[(long long)j * E3 + DIM]);
    }
    ql[idx] = __float2bfloat16(sq * (0.125f / 16.0f));
    kl[idx] = __float2bfloat16(sk * (1.0f / 16.0f));
}

// ---------------------------------------------------------------------------
// Softmax over rows of 256 (warp per row)
// ---------------------------------------------------------------------------
__global__ void softmax256_kernel(bf16* __restrict__ data, int rows) {
    int row = blockIdx.x * 8 + threadIdx.y;
    if (row >= rows) return;
    uint32_t* p = (uint32_t*)(data + (long long)row * 256);
    int lane = threadIdx.x;
    float2 v[4];
    #pragma unroll
    for (int j = 0; j < 4; j++) {
        uint32_t wv = p[lane + j * 32];
        v[j] = __bfloat1622float2(*(__nv_bfloat162*)&wv);
    }
    float mx = -FLT_MAX;
    #pragma unroll
    for (int j = 0; j < 4; j++) mx = fmaxf(mx, fmaxf(v[j].x, v[j].y));
    #pragma unroll
    for (int o = 16; o; o >>= 1) mx = fmaxf(mx, __shfl_xor_sync(0xffffffffu, mx, o));
    float s = 0.f;
    #pragma unroll
    for (int j = 0; j < 4; j++) {
        v[j].x = expf(v[j].x - mx); v[j].y = expf(v[j].y - mx);
        s += v[j].x + v[j].y;
    }
    #pragma unroll
    for (int o = 16; o; o >>= 1) s += __shfl_xor_sync(0xffffffffu, s, o);
    float inv = 1.0f / s;
    #pragma unroll
    for (int j = 0; j < 4; j++)
        p[lane + j * 32] = packbf(v[j].x * inv, v[j].y * inv);
}

// ---------------------------------------------------------------------------
// Softmax over rows of 4096 (block per row)
// ---------------------------------------------------------------------------
__global__ void softmax4096_kernel(bf16* __restrict__ data) {
    __shared__ float sm[32];
    uint32_t* p = (uint32_t*)(data + (long long)blockIdx.x * N_TOK);
    int t = threadIdx.x;
    float2 v[8];
    #pragma unroll
    for (int j = 0; j < 8; j++) {
        uint32_t wv = p[t + j * 256];
        v[j] = __bfloat1622float2(*(__nv_bfloat162*)&wv);
    }
    float mx = -FLT_MAX;
    #pragma unroll
    for (int j = 0; j < 8; j++) mx = fmaxf(mx, fmaxf(v[j].x, v[j].y));
    mx = bredMax(mx, sm);
    float s = 0.f;
    #pragma unroll
    for (int j = 0; j < 8; j++) {
        v[j].x = expf(v[j].x - mx); v[j].y = expf(v[j].y - mx);
        s += v[j].x + v[j].y;
    }
    s = bredSum(s, sm);
    float inv = 1.0f / s;
    #pragma unroll
    for (int j = 0; j < 8; j++)
        p[t + j * 256] = packbf(v[j].x * inv, v[j].y * inv);
}

// ---------------------------------------------------------------------------
// pinv helpers
// ---------------------------------------------------------------------------
__global__ void reset_kernel(float* scal) {
    if (threadIdx.x < 2) scal[threadIdx.x] = 0.0f;
}

__global__ void pinv_reduce_kernel(const bf16* __restrict__ a2, float* __restrict__ scal) {
    int bh = blockIdx.x, j = threadIdx.x;
    const bf16* a = a2 + (long long)bh * (M_LM * M_LM);
    float cs = 0.f, rs = 0.f;
    for (int i = 0; i < M_LM; i++) {
        cs += fabsf(__bfloat162float(a[i * M_LM + j]));
        rs += fabsf(__bfloat162float(a[j * M_LM + i]));
    }
    atomicMax((int*)&scal[0], __float_as_int(rs));
    atomicMax((int*)&scal[1], __float_as_int(cs));
}

__global__ void zinit_kernel(const bf16* __restrict__ a2, bf16* __restrict__ z,
                             const float* __restrict__ scal) {
    float inv = 1.0f / (scal[0] * scal[1]);
    int idx = blockIdx.x * 256 + threadIdx.x;
    int bh = idx >> 16, r = (idx >> 8) & 255, c = idx & 255;
    z[idx] = __float2bfloat16(
        __bfloat162float(a2[((long long)bh << 16) + (c << 8) + r]) * inv);
}

__global__ void idminus_kernel(const bf16* __restrict__ in, bf16* __restrict__ out,
                               float alpha) {
    int idx = blockIdx.x * 256 + threadIdx.x;
    int r = (idx >> 8) & 255, c = idx & 255;
    out[idx] = __float2bfloat16(((r == c) ? alpha : 0.0f) - __bfloat162float(in[idx]));
}

// ---------------------------------------------------------------------------
// Depthwise residual conv, smem-tiled: block = (128-seq chunk, bh)
// ---------------------------------------------------------------------------
#define CONV_TI 128
__global__ void __launch_bounds__(256)
conv_add_kernel(const bf16* __restrict__ qkv, const float* __restrict__ cw,
                bf16* __restrict__ Y) {
    __shared__ float w[KER];
    __shared__ __align__(16) bf16 vs[(CONV_TI + 32) * 64];
    int bh = blockIdx.y;
    int bb = bh >> 3, h = bh & 7;
    int i0 = blockIdx.x * CONV_TI;
    int tid = threadIdx.x;
    if (tid < KER) w[tid] = cw[h * KER + tid];

    const bf16* vbase = qkv + (long long)bb * N_TOK * E3 + 2 * DIM + h * DH;
    #pragma unroll
    for (int c = 0; c < 5; c++) {
        int chunk = tid + c * 256;            // 0..1279: 160 rows x 8 chunks
        int row = chunk >> 3, ch = chunk & 7;
        int r = i0 - 16 + row;
        uint4 val = make_uint4(0, 0, 0, 0);
        if (r >= 0 && r < N_TOK)
            val = *(const uint4*)(vbase + (long long)r * E3 + ch * 8);
        *(uint4*)(&vs[row * 64 + ch * 8]) = val;
    }
    __syncthreads();

    int j = tid & 63, iy = tid >> 6;          // 64 cols x 4 row-groups
    #pragma unroll
    for (int s = 0; s < CONV_TI / 4; s++) {
        int ii = iy + s * 4;
        float acc = 0.f;
        #pragma unroll
        for (int t = 0; t < KER; t++)
            acc += w[t] * __bfloat162float(vs[(ii + t) * 64 + j]);
        long long o = ((long long)(bb * N_TOK + i0 + ii)) * DIM + h * DH + j;
        Y[o] = __float2bfloat16(__bfloat162float(Y[o]) + acc);
    }
}

// ---------------------------------------------------------------------------
// Final epilogue (fp32)
// ---------------------------------------------------------------------------
__global__ void final_ep_kernel(const float* __restrict__ x, const float* __restrict__ ob,
                                const float* __restrict__ omega, float* __restrict__ out) {
    long long idx = (long long)blockIdx.x * 256 + threadIdx.x;
    out[idx] = x[idx] * omega[0] + out[idx] + ob[idx & (DIM - 1)];
}

// ---------------------------------------------------------------------------
// Launcher
// ---------------------------------------------------------------------------
template <typename T, size_t N>
static T* symp(T (&s)[N]) {
    void* p = nullptr;
    cudaGetSymbolAddress(&p, s);
    return (T*)p;
}

extern "C" void kernel_launch(void* const* d_in, const int* in_sizes, int n_in,
                              void* d_out, int out_size) {
    const float* x      = (const float*)d_in[0];
    const float* ln_w   = (const float*)d_in[1];
    const float* ln_b   = (const float*)d_in[2];
    const float* qkv_w  = (const float*)d_in[3];
    const float* out_w  = (const float*)d_in[4];
    const float* out_b  = (const float*)d_in[5];
    const float* conv_w = (const float*)d_in[6];
    const float* omega  = (const float*)d_in[7];
    float* out = (float*)d_out;

    bf16* xn    = symp(g_xn);
    bf16* qkv   = symp(g_qkv);
    bf16* ql    = symp(g_ql);
    bf16* kl    = symp(g_kl);
    bf16* attn1 = symp(g_attn1);
    bf16* attn3 = symp(g_attn3);
    bf16* o1    = symp(g_o1);
    bf16* a2    = symp(g_a2);
    bf16* z     = symp(g_z);
    bf16* z2    = symp(g_z2);
    bf16* az    = symp(g_az);
    bf16* t1    = symp(g_t1);
    bf16* t2    = symp(g_t2);
    bf16* kv    = symp(g_kv);
    bf16* Y     = symp(g_y);
    bf16* qkvwb = symp(g_qkvw);
    bf16* outwb = symp(g_outw);
    float* scal = symp(g_scal);

    const long long sA1 = (long long)N_TOK * M_LM;
    const long long sLM = (long long)M_LM * DH;
    const long long sMM = (long long)M_LM * M_LM;
    const long long sQB = (long long)N_TOK * E3;

    // 0. Weight conversion fp32 -> bf16
    f2b_kernel<<<(E3 * DIM / 4 + 255) / 256, 256>>>((const float4*)qkv_w, (uint2*)qkvwb,
                                                    E3 * DIM / 4);
    f2b_kernel<<<(DIM * DIM / 4 + 255) / 256, 256>>>((const float4*)out_w, (uint2*)outwb,
                                                     DIM * DIM / 4);

    // 1. LayerNorm
    ln_kernel<<<BN, 256>>>(x, ln_w, ln_b, xn);

    // 2. QKV projection
    launch_b128(true, xn, qkvwb, qkv, BN, E3, DIM, DIM, DIM, E3,
                0, 0, 0, 0, 0, 0, 1, 1, 1.0f, 0.0f);

    // 3. Landmark means
    landmark_kernel<<<(BHN * M_LM * DH) / 256, 256>>>(qkv, ql, kl);

    // 4. sim1 -> softmax -> attn1
    launch_b128(true, qkv, kl, attn1, N_TOK, M_LM, DH, E3, DH, M_LM,
                sQB, DH, 8 * sLM, sLM, 8 * sA1, sA1, HEADS, BHN, 0.125f, 0.0f);
    softmax256_kernel<<<(BHN * N_TOK) / 8, dim3(32, 8)>>>(attn1, BHN * N_TOK);

    // 5. sim2 -> softmax -> a2
    launch_b128(true, ql, kl, a2, M_LM, M_LM, DH, DH, DH, M_LM,
                8 * sLM, sLM, 8 * sLM, sLM, 8 * sMM, sMM, HEADS, BHN, 1.0f, 0.0f);
    softmax256_kernel<<<(BHN * M_LM) / 8, dim3(32, 8)>>>(a2, BHN * M_LM);

    // 6. sim3 -> softmax -> attn3
    launch_b128(true, ql, qkv + DIM, attn3, M_LM, N_TOK, DH, DH, E3, N_TOK,
                8 * sLM, sLM, sQB, DH, 8 * sA1, sA1, HEADS, BHN, 1.0f, 0.0f);
    softmax4096_kernel<<<BHN * M_LM, 256>>>(attn3);

    // 7. pinv (6 Newton-Schulz iterations)
    reset_kernel<<<1, 32>>>(scal);
    pinv_reduce_kernel<<<BHN, 256>>>(a2, scal);
    zinit_kernel<<<(BHN * (int)sMM) / 256, 256>>>(a2, z, scal);

    bf16* zc = z;
    bf16* zn = z2;
    const int eg = (BHN * (int)sMM) / 256;
    for (int it = 0; it < 6; it++) {
        launch_b128(false, a2, zc, az, M_LM, M_LM, M_LM, M_LM, M_LM, M_LM,
                    sMM, 0, sMM, 0, sMM, 0, 1, BHN, 1.0f, 0.0f);
        idminus_kernel<<<eg, 256>>>(az, t1, 7.0f);
        launch_b128(false, az, t1, t2, M_LM, M_LM, M_LM, M_LM, M_LM, M_LM,
                    sMM, 0, sMM, 0, sMM, 0, 1, BHN, -1.0f, 15.0f);
        launch_b128(false, az, t2, t1, M_LM, M_LM, M_LM, M_LM, M_LM, M_LM,
                    sMM, 0, sMM, 0, sMM, 0, 1, BHN, -1.0f, 13.0f);
        launch_b128(false, zc, t1, zn, M_LM, M_LM, M_LM, M_LM, M_LM, M_LM,
                    sMM, 0, sMM, 0, sMM, 0, 1, BHN, 0.25f, 0.0f);
        bf16* tmp = zc; zc = zn; zn = tmp;
    }

    // 8. kv = attn3 @ v
    launch_b64(false, attn3, qkv + 2 * DIM, kv, M_LM, DH, N_TOK, N_TOK, E3, DH,
               8 * sA1, sA1, sQB, DH, 8 * sLM, sLM, HEADS, BHN, 1.0f, 0.0f);

    // 9. o1 = attn1 @ attn2_inv
    launch_b128(false, attn1, zc, o1, N_TOK, M_LM, M_LM, M_LM, M_LM, M_LM,
                8 * sA1, sA1, 8 * sMM, sMM, 8 * sA1, sA1, HEADS, BHN, 1.0f, 0.0f);

    // 10. Y = o1 @ kv (written in [b,n,h*dh] layout)
    launch_b64(false, o1, kv, Y, N_TOK, DH, M_LM, M_LM, DH, DIM,
               8 * sA1, sA1, 8 * sLM, sLM, (long long)N_TOK * DIM, DH,
               HEADS, BHN, 1.0f, 0.0f);

    // 11. conv residual (smem-tiled)
    conv_add_kernel<<<dim3(N_TOK / CONV_TI, BHN), 256>>>(qkv, conv_w, Y);

    // 12. out projection (fp32 output)
    {
        dim3 grid(DIM / 128, BN / 128, 1), block(256);
        bgemm_kernel<true, 32, true><<<grid, block>>>(Y, outwb, (void*)out,
            DIM, DIM, DIM, DIM, 0, 0, 0, 0, 0, 0, 1, 1.0f, 0.0f);
    }

    // 13. final residual
    final_ep_kernel<<<(BN * DIM) / 256, 256>>>(x, out_b, omega, out);
}